// round 9
// baseline (speedup 1.0000x reference)
#include <cuda_runtime.h>
#include <cuda_bf16.h>
#include <math_constants.h>
#include <cstdint>

// Problem dims (fixed)
#define BB 2
#define SS 2048
#define DD 768
#define HH 12
#define DH 64
#define BH (BB*HH)          // 24
#define ROWS_TOTAL (BB*HH*SS) // 49152

typedef unsigned long long u64;

// ---- packed f32x2 helpers (Blackwell FFMA2 path) --------------------------
__device__ __forceinline__ u64 dup2(float v) {
    u64 r; asm("mov.b64 %0, {%1, %1};" : "=l"(r) : "f"(v)); return r;
}
__device__ __forceinline__ void fma2(u64& d, u64 a, u64 b) {
    asm("fma.rn.f32x2 %0, %1, %2, %0;" : "+l"(d) : "l"(a), "l"(b));
}
__device__ __forceinline__ float2 unpack2(u64 v) {
    float2 r; asm("mov.b64 {%0, %1}, %2;" : "=f"(r.x), "=f"(r.y) : "l"(v)); return r;
}

// Scratch (device globals: sanctioned scratch mechanism)
__device__ __nv_bfloat16 g_qh[BB*HH*SS*DH];  // Q*0.125 split-hi
__device__ __nv_bfloat16 g_ql[BB*HH*SS*DH];  // Q*0.125 split-lo
__device__ __nv_bfloat16 g_kh[BB*HH*SS*DH];
__device__ __nv_bfloat16 g_kl[BB*HH*SS*DH];
__device__ __nv_bfloat16 g_vth[BB*HH*DH*SS]; // V^T [bh][d][s] split-hi
__device__ __nv_bfloat16 g_vtl[BB*HH*DH*SS]; // V^T split-lo
__device__ float g_m[ROWS_TOTAL];
__device__ float g_l[ROWS_TOTAL];

__device__ __forceinline__ uint32_t smem_u32(const void* p) {
    uint32_t a;
    asm("{ .reg .u64 t; cvta.to.shared.u64 t, %1; cvt.u32.u64 %0, t; }" : "=r"(a) : "l"(p));
    return a;
}
__device__ __forceinline__ void ldmx4(uint32_t* r, uint32_t addr) {
    asm volatile("ldmatrix.sync.aligned.m8n8.x4.shared.b16 {%0,%1,%2,%3}, [%4];"
        : "=r"(r[0]), "=r"(r[1]), "=r"(r[2]), "=r"(r[3]) : "r"(addr));
}
__device__ __forceinline__ void mma16816(float* c, const uint32_t* a, uint32_t b0, uint32_t b1) {
    asm volatile(
        "mma.sync.aligned.m16n8k16.row.col.f32.bf16.bf16.f32 "
        "{%0,%1,%2,%3},{%4,%5,%6,%7},{%8,%9},{%0,%1,%2,%3};"
        : "+f"(c[0]), "+f"(c[1]), "+f"(c[2]), "+f"(c[3])
        : "r"(a[0]), "r"(a[1]), "r"(a[2]), "r"(a[3]), "r"(b0), "r"(b1));
}
__device__ __forceinline__ uint32_t pack_bf2(__nv_bfloat16 a, __nv_bfloat16 b) {
    return (uint32_t)__bfloat16_as_ushort(a) | ((uint32_t)__bfloat16_as_ushort(b) << 16);
}

// ---------------------------------------------------------------------------
// K1: QKV projection. q,k as bf16 hi/lo splits (q pre-scaled 0.125);
// v as bf16 hi/lo splits in TRANSPOSED layout [bh][d][s].
// ---------------------------------------------------------------------------
__global__ __launch_bounds__(256) void qkv_kernel(
    const float* __restrict__ hid,
    const float* __restrict__ Wq, const float* __restrict__ bq,
    const float* __restrict__ Wk, const float* __restrict__ bk,
    const float* __restrict__ Wv, const float* __restrict__ bv)
{
    const float* W; const float* bias;
    if (blockIdx.z == 0)      { W = Wq; bias = bq; }
    else if (blockIdx.z == 1) { W = Wk; bias = bk; }
    else                      { W = Wv; bias = bv; }

    __shared__ __align__(16) float As[16][128+4];
    __shared__ __align__(16) float Bs[16][128+4];

    const int tid = threadIdx.x;
    const int m0 = blockIdx.y * 128;
    const int n0 = blockIdx.x * 128;

    const int lr = tid >> 2;          // 0..63
    const int lc = (tid & 3) << 2;    // 0,4,8,12
    const int ty = tid >> 4;          // 0..15
    const int tx = tid & 15;          // 0..15

    u64 acc2[8][4];                   // [i][j-pair]
#pragma unroll
    for (int i = 0; i < 8; i++)
#pragma unroll
        for (int j = 0; j < 4; j++) acc2[i][j] = 0ull;

    for (int k0 = 0; k0 < DD; k0 += 16) {
#pragma unroll
        for (int r = 0; r < 2; r++) {
            int row = lr + r*64;
            float4 a = *(const float4*)(hid + (size_t)(m0+row)*DD + k0 + lc);
            As[lc+0][row]=a.x; As[lc+1][row]=a.y; As[lc+2][row]=a.z; As[lc+3][row]=a.w;
            float4 w = *(const float4*)(W + (size_t)(n0+row)*DD + k0 + lc);
            Bs[lc+0][row]=w.x; Bs[lc+1][row]=w.y; Bs[lc+2][row]=w.z; Bs[lc+3][row]=w.w;
        }
        __syncthreads();
#pragma unroll
        for (int k = 0; k < 16; k++) {
            float4 a0 = *(const float4*)&As[k][ty*8];
            float4 a1 = *(const float4*)&As[k][ty*8+4];
            u64 ra2[8];
            ra2[0]=dup2(a0.x); ra2[1]=dup2(a0.y); ra2[2]=dup2(a0.z); ra2[3]=dup2(a0.w);
            ra2[4]=dup2(a1.x); ra2[5]=dup2(a1.y); ra2[6]=dup2(a1.z); ra2[7]=dup2(a1.w);
            ulonglong2 b0 = *(const ulonglong2*)&Bs[k][tx*8];
            ulonglong2 b1 = *(const ulonglong2*)&Bs[k][tx*8+4];
            u64 rb2[4] = { b0.x, b0.y, b1.x, b1.y };
#pragma unroll
            for (int i = 0; i < 8; i++)
#pragma unroll
                for (int j = 0; j < 4; j++)
                    fma2(acc2[i][j], ra2[i], rb2[j]);
        }
        __syncthreads();
    }

    if (blockIdx.z == 2) {
        // V: transposed bf16 hi/lo: idx = ((bh)*DH + d)*SS + s
#pragma unroll
        for (int i = 0; i < 8; i++) {
            int m = m0 + ty*8 + i;
            int b = m >> 11, s = m & 2047;
#pragma unroll
            for (int j2 = 0; j2 < 4; j2++) {
                float2 p = unpack2(acc2[i][j2]);
                int n = n0 + tx*8 + j2*2;
#pragma unroll
                for (int e = 0; e < 2; e++) {
                    int ne = n + e;
                    float x = (e == 0 ? p.x : p.y) + bias[ne];
                    __nv_bfloat16 hi = __float2bfloat16(x);
                    __nv_bfloat16 lo = __float2bfloat16(x - __bfloat162float(hi));
                    int h = ne >> 6, d = ne & 63;
                    size_t idx = ((size_t)((b*HH + h)*DH + d))*SS + s;
                    g_vth[idx] = hi;
                    g_vtl[idx] = lo;
                }
            }
        }
    } else {
        const float sc = (blockIdx.z == 0) ? 0.125f : 1.0f;
        __nv_bfloat16* oh = (blockIdx.z == 0) ? g_qh : g_kh;
        __nv_bfloat16* ol = (blockIdx.z == 0) ? g_ql : g_kl;
#pragma unroll
        for (int i = 0; i < 8; i++) {
            int m = m0 + ty*8 + i;
            int b = m >> 11, s = m & 2047;
#pragma unroll
            for (int j2 = 0; j2 < 4; j2++) {
                float2 p = unpack2(acc2[i][j2]);
                int n = n0 + tx*8 + j2*2;
#pragma unroll
                for (int e = 0; e < 2; e++) {
                    int ne = n + e;
                    float x = ((e == 0 ? p.x : p.y) + bias[ne]) * sc;
                    __nv_bfloat16 hi = __float2bfloat16(x);
                    __nv_bfloat16 lo = __float2bfloat16(x - __bfloat162float(hi));
                    int h = ne >> 6, d = ne & 63;
                    size_t idx = (((size_t)(b*HH + h)*SS + s) << 6) + d;
                    oh[idx] = hi;
                    ol[idx] = lo;
                }
            }
        }
    }
}

// ---------------------------------------------------------------------------
// K2 (mma.sync HMMA): scores = Qs K^T + res  (Q pre-scaled 1/8, bf16 3-split)
// ---------------------------------------------------------------------------
#define SMM_SMEM (4*16384)

__global__ __launch_bounds__(256) void scores_mma_kernel(
    const float* __restrict__ res, float* __restrict__ out_scores)
{
    extern __shared__ __align__(1024) char smem[];
    const int OF_QH = 0, OF_QL = 16384, OF_KH = 32768, OF_KL = 49152;

    const int tid = threadIdx.x;
    const int bh = blockIdx.z;
    const int m0 = blockIdx.y * 128;
    const int n0 = blockIdx.x * 128;
    const uint32_t sb = smem_u32(smem);

    {
        const uint4* sqh = (const uint4*)(g_qh + (size_t)(bh*SS + m0)*DH);
        const uint4* sql = (const uint4*)(g_ql + (size_t)(bh*SS + m0)*DH);
        const uint4* skh = (const uint4*)(g_kh + (size_t)(bh*SS + n0)*DH);
        const uint4* skl = (const uint4*)(g_kl + (size_t)(bh*SS + n0)*DH);
        for (int idx = tid; idx < 1024; idx += 256) {
            uint32_t off = (uint32_t)idx * 16;
            uint32_t sw = off ^ ((off >> 3) & 0x70);
            *(uint4*)(smem + OF_QH + sw) = sqh[idx];
            *(uint4*)(smem + OF_QL + sw) = sql[idx];
            *(uint4*)(smem + OF_KH + sw) = skh[idx];
            *(uint4*)(smem + OF_KL + sw) = skl[idx];
        }
    }
    __syncthreads();

    const int wid = tid >> 5, lane = tid & 31;
    const int wm = wid & 3, wn = wid >> 2;
    const int mw0 = wm * 32;
    const int nw0 = wn * 64;

    float acc[2][8][4];
#pragma unroll
    for (int i = 0; i < 2; i++)
#pragma unroll
        for (int j = 0; j < 8; j++)
#pragma unroll
            for (int q = 0; q < 4; q++) acc[i][j][q] = 0.f;

    const int lrow = lane & 15;
    const int lkh  = (lane >> 4) * 16;

    const int aoffs[3] = { OF_QH, OF_QH, OF_QL };
    const int boffs[3] = { OF_KH, OF_KL, OF_KH };

#pragma unroll
    for (int s = 0; s < 3; s++) {
        const int aOff = aoffs[s], bOff = boffs[s];
#pragma unroll
        for (int ks = 0; ks < 4; ks++) {
            const uint32_t colb = (uint32_t)(ks*32 + lkh);
            uint32_t af[2][4];
#pragma unroll
            for (int mi = 0; mi < 2; mi++) {
                uint32_t off = (uint32_t)(mw0 + mi*16 + lrow) * 128 + colb;
                uint32_t sw = off ^ ((off >> 3) & 0x70);
                ldmx4(af[mi], sb + aOff + sw);
            }
            uint32_t bf[4][4];
#pragma unroll
            for (int nj = 0; nj < 4; nj++) {
                uint32_t off = (uint32_t)(nw0 + nj*16 + lrow) * 128 + colb;
                uint32_t sw = off ^ ((off >> 3) & 0x70);
                ldmx4(bf[nj], sb + bOff + sw);
            }
#pragma unroll
            for (int mi = 0; mi < 2; mi++)
#pragma unroll
                for (int nj = 0; nj < 4; nj++) {
                    mma16816(acc[mi][nj*2+0], af[mi], bf[nj][0], bf[nj][2]);
                    mma16816(acc[mi][nj*2+1], af[mi], bf[nj][1], bf[nj][3]);
                }
        }
    }

    const float* R = res + (size_t)bh * SS * SS;
    float* O = out_scores + (size_t)bh * SS * SS;
#pragma unroll
    for (int mi = 0; mi < 2; mi++) {
#pragma unroll
        for (int half = 0; half < 2; half++) {
            int m = m0 + mw0 + mi*16 + (lane >> 2) + half*8;
            const float* rrow = R + (size_t)m * SS + n0 + nw0 + (lane & 3)*2;
            float* orow = O + (size_t)m * SS + n0 + nw0 + (lane & 3)*2;
#pragma unroll
            for (int nj = 0; nj < 8; nj++) {
                float2 r = *(const float2*)(rrow + nj*8);
                float2 o;
                o.x = acc[mi][nj][half*2+0] + r.x;
                o.y = acc[mi][nj][half*2+1] + r.y;
                *(float2*)(orow + nj*8) = o;
            }
        }
    }
}

// ---------------------------------------------------------------------------
// K3: per-row softmax stats over (scores + mask): rowmax m, sum l
// ---------------------------------------------------------------------------
__device__ __forceinline__ float warpRedMax(float v) {
#pragma unroll
    for (int o = 16; o > 0; o >>= 1) v = fmaxf(v, __shfl_xor_sync(0xffffffffu, v, o));
    return v;
}
__device__ __forceinline__ float warpRedSum(float v) {
#pragma unroll
    for (int o = 16; o > 0; o >>= 1) v += __shfl_xor_sync(0xffffffffu, v, o);
    return v;
}

__global__ __launch_bounds__(256) void softmax_stats_kernel(
    const float* __restrict__ scores, const float* __restrict__ mask)
{
    const int tid = threadIdx.x;
    __shared__ float red[8];

#pragma unroll
    for (int rr = 0; rr < 4; rr++) {
        const int row = blockIdx.x * 4 + rr;
        const int b = row / (HH*SS);
        const float* sr = scores + (size_t)row * SS;
        const float* mr = mask + (size_t)b * SS;

        float vals[8];
        float lm = -CUDART_INF_F;
#pragma unroll
        for (int i = 0; i < 8; i++) {
            int c = tid + i*256;
            float v = sr[c] + mr[c];
            vals[i] = v;
            lm = fmaxf(lm, v);
        }

        float wm = warpRedMax(lm);
        if ((tid & 31) == 0) red[tid >> 5] = wm;
        __syncthreads();
        float bm = red[0];
#pragma unroll
        for (int w = 1; w < 8; w++) bm = fmaxf(bm, red[w]);

        float ls = 0.f;
#pragma unroll
        for (int i = 0; i < 8; i++) ls += __expf(vals[i] - bm);
        __syncthreads();
        float ws = warpRedSum(ls);
        if ((tid & 31) == 0) red[tid >> 5] = ws;
        __syncthreads();
        if (tid == 0) {
            float s = 0.f;
#pragma unroll
            for (int w = 0; w < 8; w++) s += red[w];
            g_m[row] = bm;
            g_l[row] = s;
        }
        __syncthreads();
    }
}

// ---------------------------------------------------------------------------
// K4 (mma.sync HMMA): ctx = softmax(scores+mask) @ V.
// Per CTA: 128(m) x 64(n=DH), K=2048 in 16 chunks of 128.
// Warps: 4(m-groups) x 2(k-split). P bf16 hi/lo generated on the fly;
// V^T bf16 hi/lo preconverted. 3-split: Ph*Vh + Ph*Vl + Pl*Vh.
// smem: PH[2][128][64] PL[2][128][64] VH[2][64][64] VL[2][64][64] + stats
// ---------------------------------------------------------------------------
#define PV_OF_PH 0
#define PV_OF_PL 32768
#define PV_OF_VH 65536
#define PV_OF_VL 81920
#define PV_OF_MS 98304
#define PV_OF_RL (98304 + 512)
#define PV_SMEM  (98304 + 1024)

__global__ __launch_bounds__(256) void pv_mma_kernel(
    const float* __restrict__ scores, const float* __restrict__ mask,
    float* __restrict__ ctx)
{
    extern __shared__ __align__(1024) char smem[];
    const int tid = threadIdx.x;
    const int bh = blockIdx.z;
    const int b = bh / HH, h = bh % HH;
    const int m0 = blockIdx.y * 128;
    const uint32_t sb = smem_u32(smem);

    float* ms  = (float*)(smem + PV_OF_MS);
    float* rls = (float*)(smem + PV_OF_RL);
    if (tid < 128) {
        int r = bh*SS + m0 + tid;
        ms[tid]  = g_m[r];
        rls[tid] = 1.0f / g_l[r];
    }
    __syncthreads();

    const int wid = tid >> 5, lane = tid & 31;
    const int wm = wid & 3, wk = wid >> 2;
    const int mw0 = wm * 32;
    const int lrow = lane & 15;
    const int lkh  = (lane >> 4) * 16;

    // P-gen thread mapping: row pr, k-half hf
    const int pr = tid >> 1;
    const int hf = tid & 1;
    const float mrow = ms[pr];
    const float* srow = scores + (size_t)bh*SS*SS + (size_t)(m0 + pr)*SS;
    const float* mrow_ptr = mask + (size_t)b*SS;

    float acc[2][8][4];
#pragma unroll
    for (int i = 0; i < 2; i++)
#pragma unroll
        for (int j = 0; j < 8; j++)
#pragma unroll
            for (int q = 0; q < 4; q++) acc[i][j][q] = 0.f;

    const __nv_bfloat16* vth = g_vth + (size_t)(bh*DH)*SS;
    const __nv_bfloat16* vtl = g_vtl + (size_t)(bh*DH)*SS;

    for (int kc = 0; kc < 16; kc++) {
        const int kc0 = kc * 128;

        // --- load V subtiles: VH/VL [sub][d][kk], 128B rows, SW128 swizzle
        for (int i = tid; i < 1024; i += 256) {
            int sub = i >> 9;          // 0/1
            int rem = i & 511;
            int d = rem >> 3, u = rem & 7;
            size_t g = (size_t)d * SS + kc0 + sub*64 + u*8;
            uint32_t off = (uint32_t)(d*128 + u*16);
            uint32_t sw = off ^ ((off >> 3) & 0x70);
            *(uint4*)(smem + PV_OF_VH + sub*8192 + sw) = *(const uint4*)(vth + g);
            *(uint4*)(smem + PV_OF_VL + sub*8192 + sw) = *(const uint4*)(vtl + g);
        }

        // --- generate P tile: row pr, cols kc0 + hf*64 + [0..64)
        {
            const float* sc = srow + kc0 + hf*64;
            const float* mk = mrow_ptr + kc0 + hf*64;
            const int pbase = hf * 16384;
#pragma unroll
            for (int u = 0; u < 8; u++) {
                float4 s0 = *(const float4*)(sc + u*8);
                float4 s1 = *(const float4*)(sc + u*8 + 4);
                float4 k0v = *(const float4*)(mk + u*8);
                float4 k1v = *(const float4*)(mk + u*8 + 4);
                float e[8];
                e[0] = __expf(s0.x + k0v.x - mrow);
                e[1] = __expf(s0.y + k0v.y - mrow);
                e[2] = __expf(s0.z + k0v.z - mrow);
                e[3] = __expf(s0.w + k0v.w - mrow);
                e[4] = __expf(s1.x + k1v.x - mrow);
                e[5] = __expf(s1.y + k1v.y - mrow);
                e[6] = __expf(s1.z + k1v.z - mrow);
                e[7] = __expf(s1.w + k1v.w - mrow);
                __nv_bfloat16 hi[8]; float lo[8];
#pragma unroll
                for (int t = 0; t < 8; t++) {
                    hi[t] = __float2bfloat16(e[t]);
                    lo[t] = e[t] - __bfloat162float(hi[t]);
                }
                uint4 hp, lp;
                hp.x = pack_bf2(hi[0], hi[1]); hp.y = pack_bf2(hi[2], hi[3]);
                hp.z = pack_bf2(hi[4], hi[5]); hp.w = pack_bf2(hi[6], hi[7]);
                lp.x = pack_bf2(__float2bfloat16(lo[0]), __float2bfloat16(lo[1]));
                lp.y = pack_bf2(__float2bfloat16(lo[2]), __float2bfloat16(lo[3]));
                lp.z = pack_bf2(__float2bfloat16(lo[4]), __float2bfloat16(lo[5]));
                lp.w = pack_bf2(__float2bfloat16(lo[6]), __float2bfloat16(lo[7]));
                uint32_t off = (uint32_t)(pr*128 + u*16);
                uint32_t sw = off ^ ((off >> 3) & 0x70);
                *(uint4*)(smem + PV_OF_PH + pbase + sw) = hp;
                *(uint4*)(smem + PV_OF_PL + pbase + sw) = lp;
            }
        }
        __syncthreads();

        // --- HMMA: warp (wm, wk) on P sub[wk] x V sub[wk]
        {
            const uint32_t aH = sb + PV_OF_PH + wk*16384;
            const uint32_t aL = sb + PV_OF_PL + wk*16384;
            const uint32_t bHb = sb + PV_OF_VH + wk*8192;
            const uint32_t bLb = sb + PV_OF_VL + wk*8192;
#pragma unroll
            for (int ks = 0; ks < 4; ks++) {
                const uint32_t colb = (uint32_t)(ks*32 + lkh);
                uint32_t ah[2][4], al[2][4];
#pragma unroll
                for (int mi = 0; mi < 2; mi++) {
                    uint32_t off = (uint32_t)(mw0 + mi*16 + lrow) * 128 + colb;
                    uint32_t sw = off ^ ((off >> 3) & 0x70);
                    ldmx4(ah[mi], aH + sw);
                    ldmx4(al[mi], aL + sw);
                }
                uint32_t bh_[4][4], bl_[4][4];
#pragma unroll
                for (int nj = 0; nj < 4; nj++) {
                    uint32_t off = (uint32_t)(nj*16 + lrow) * 128 + colb;
                    uint32_t sw = off ^ ((off >> 3) & 0x70);
                    ldmx4(bh_[nj], bHb + sw);
                    ldmx4(bl_[nj], bLb + sw);
                }
#pragma unroll
                for (int mi = 0; mi < 2; mi++)
#pragma unroll
                    for (int nj = 0; nj < 4; nj++) {
                        mma16816(acc[mi][nj*2+0], ah[mi], bh_[nj][0], bh_[nj][2]);
                        mma16816(acc[mi][nj*2+1], ah[mi], bh_[nj][1], bh_[nj][3]);
                        mma16816(acc[mi][nj*2+0], ah[mi], bl_[nj][0], bl_[nj][2]);
                        mma16816(acc[mi][nj*2+1], ah[mi], bl_[nj][1], bl_[nj][3]);
                        mma16816(acc[mi][nj*2+0], al[mi], bh_[nj][0], bh_[nj][2]);
                        mma16816(acc[mi][nj*2+1], al[mi], bh_[nj][1], bh_[nj][3]);
                    }
            }
        }
        __syncthreads();
    }

    // --- reduce k-groups: wk=1 warps dump acc to smem, wk=0 adds.
    float* scr = (float*)(smem + PV_OF_PH);   // reuse, 32 KB needed
    if (wk == 1) {
#pragma unroll
        for (int mi = 0; mi < 2; mi++)
#pragma unroll
            for (int nj = 0; nj < 8; nj++) {
                int idx = ((wm*32 + lane)*16 + mi*8 + nj)*4;
                *(float4*)(scr + idx) = *(const float4*)acc[mi][nj];
            }
    }
    __syncthreads();
    if (wk == 0) {
#pragma unroll
        for (int mi = 0; mi < 2; mi++)
#pragma unroll
            for (int nj = 0; nj < 8; nj++) {
                int idx = ((wm*32 + lane)*16 + mi*8 + nj)*4;
                float4 o = *(const float4*)(scr + idx);
                acc[mi][nj][0] += o.x; acc[mi][nj][1] += o.y;
                acc[mi][nj][2] += o.z; acc[mi][nj][3] += o.w;
            }
        // epilogue: scale 1/l, write ctx
#pragma unroll
        for (int mi = 0; mi < 2; mi++) {
#pragma unroll
            for (int half = 0; half < 2; half++) {
                int lm = mw0 + mi*16 + (lane >> 2) + half*8;    // 0..127
                int m = m0 + lm;
                float rl = rls[lm];
                float* orow = ctx + ((size_t)b*SS + m)*DD + h*DH + (lane & 3)*2;
#pragma unroll
                for (int nj = 0; nj < 8; nj++) {
                    float2 o;
                    o.x = acc[mi][nj][half*2+0] * rl;
                    o.y = acc[mi][nj][half*2+1] * rl;
                    *(float2*)(orow + nj*8) = o;
                }
            }
        }
    }
}

// ---------------------------------------------------------------------------
extern "C" void kernel_launch(void* const* d_in, const int* in_sizes, int n_in,
                              void* d_out, int out_size)
{
    const float* hid  = (const float*)d_in[0];
    const float* mask = (const float*)d_in[1];
    const float* res  = (const float*)d_in[2];
    const float* Wq = (const float*)d_in[3];
    const float* bq = (const float*)d_in[4];
    const float* Wk = (const float*)d_in[5];
    const float* bk = (const float*)d_in[6];
    const float* Wv = (const float*)d_in[7];
    const float* bv = (const float*)d_in[8];

    float* out_ctx    = (float*)d_out;
    float* out_scores = (float*)d_out + (size_t)BB*SS*DD;

    cudaFuncSetAttribute(scores_mma_kernel,
                         cudaFuncAttributeMaxDynamicSharedMemorySize, SMM_SMEM);
    cudaFuncSetAttribute(pv_mma_kernel,
                         cudaFuncAttributeMaxDynamicSharedMemorySize, PV_SMEM);

    qkv_kernel<<<dim3(DD/128, (BB*SS)/128, 3), 256>>>(hid, Wq, bq, Wk, bk, Wv, bv);
    scores_mma_kernel<<<dim3(SS/128, SS/128, BH), 256, SMM_SMEM>>>(res, out_scores);
    softmax_stats_kernel<<<dim3(ROWS_TOTAL/4), 256>>>(out_scores, mask);
    pv_mma_kernel<<<dim3(1, SS/128, BH), 256, PV_SMEM>>>(out_scores, mask, out_ctx);
}

// round 10
// speedup vs baseline: 1.0564x; 1.0564x over previous
#include <cuda_runtime.h>
#include <cuda_bf16.h>
#include <math_constants.h>
#include <cstdint>

// Problem dims (fixed)
#define BB 2
#define SS 2048
#define DD 768
#define HH 12
#define DH 64
#define BH (BB*HH)          // 24
#define ROWS_TOTAL (BB*HH*SS) // 49152

typedef unsigned long long u64;

// ---- packed f32x2 helpers (Blackwell FFMA2 path) --------------------------
__device__ __forceinline__ u64 dup2(float v) {
    u64 r; asm("mov.b64 %0, {%1, %1};" : "=l"(r) : "f"(v)); return r;
}
__device__ __forceinline__ void fma2(u64& d, u64 a, u64 b) {
    asm("fma.rn.f32x2 %0, %1, %2, %0;" : "+l"(d) : "l"(a), "l"(b));
}
__device__ __forceinline__ float2 unpack2(u64 v) {
    float2 r; asm("mov.b64 {%0, %1}, %2;" : "=f"(r.x), "=f"(r.y) : "l"(v)); return r;
}

// Scratch (device globals: sanctioned scratch mechanism)
__device__ __nv_bfloat16 g_qh[BB*HH*SS*DH];  // Q*0.125 split-hi
__device__ __nv_bfloat16 g_ql[BB*HH*SS*DH];  // Q*0.125 split-lo
__device__ __nv_bfloat16 g_kh[BB*HH*SS*DH];
__device__ __nv_bfloat16 g_kl[BB*HH*SS*DH];
__device__ __nv_bfloat16 g_vth[BB*HH*DH*SS]; // V^T [bh][d][s] split-hi
__device__ __nv_bfloat16 g_vtl[BB*HH*DH*SS]; // V^T split-lo
__device__ float g_m[ROWS_TOTAL];
__device__ float g_l[ROWS_TOTAL];

__device__ __forceinline__ uint32_t smem_u32(const void* p) {
    uint32_t a;
    asm("{ .reg .u64 t; cvta.to.shared.u64 t, %1; cvt.u32.u64 %0, t; }" : "=r"(a) : "l"(p));
    return a;
}
__device__ __forceinline__ void ldmx4(uint32_t* r, uint32_t addr) {
    asm volatile("ldmatrix.sync.aligned.m8n8.x4.shared.b16 {%0,%1,%2,%3}, [%4];"
        : "=r"(r[0]), "=r"(r[1]), "=r"(r[2]), "=r"(r[3]) : "r"(addr));
}
__device__ __forceinline__ void mma16816(float* c, const uint32_t* a, uint32_t b0, uint32_t b1) {
    asm volatile(
        "mma.sync.aligned.m16n8k16.row.col.f32.bf16.bf16.f32 "
        "{%0,%1,%2,%3},{%4,%5,%6,%7},{%8,%9},{%0,%1,%2,%3};"
        : "+f"(c[0]), "+f"(c[1]), "+f"(c[2]), "+f"(c[3])
        : "r"(a[0]), "r"(a[1]), "r"(a[2]), "r"(a[3]), "r"(b0), "r"(b1));
}
__device__ __forceinline__ uint32_t pack_bf2(__nv_bfloat16 a, __nv_bfloat16 b) {
    return (uint32_t)__bfloat16_as_ushort(a) | ((uint32_t)__bfloat16_as_ushort(b) << 16);
}

// ---------------------------------------------------------------------------
// K1: QKV projection. q,k as bf16 hi/lo splits (q pre-scaled 0.125);
// v as bf16 hi/lo splits in TRANSPOSED layout [bh][d][s].
// ---------------------------------------------------------------------------
__global__ __launch_bounds__(256) void qkv_kernel(
    const float* __restrict__ hid,
    const float* __restrict__ Wq, const float* __restrict__ bq,
    const float* __restrict__ Wk, const float* __restrict__ bk,
    const float* __restrict__ Wv, const float* __restrict__ bv)
{
    const float* W; const float* bias;
    if (blockIdx.z == 0)      { W = Wq; bias = bq; }
    else if (blockIdx.z == 1) { W = Wk; bias = bk; }
    else                      { W = Wv; bias = bv; }

    __shared__ __align__(16) float As[16][128+4];
    __shared__ __align__(16) float Bs[16][128+4];

    const int tid = threadIdx.x;
    const int m0 = blockIdx.y * 128;
    const int n0 = blockIdx.x * 128;

    const int lr = tid >> 2;          // 0..63
    const int lc = (tid & 3) << 2;    // 0,4,8,12
    const int ty = tid >> 4;          // 0..15
    const int tx = tid & 15;          // 0..15

    u64 acc2[8][4];                   // [i][j-pair]
#pragma unroll
    for (int i = 0; i < 8; i++)
#pragma unroll
        for (int j = 0; j < 4; j++) acc2[i][j] = 0ull;

    for (int k0 = 0; k0 < DD; k0 += 16) {
#pragma unroll
        for (int r = 0; r < 2; r++) {
            int row = lr + r*64;
            float4 a = *(const float4*)(hid + (size_t)(m0+row)*DD + k0 + lc);
            As[lc+0][row]=a.x; As[lc+1][row]=a.y; As[lc+2][row]=a.z; As[lc+3][row]=a.w;
            float4 w = *(const float4*)(W + (size_t)(n0+row)*DD + k0 + lc);
            Bs[lc+0][row]=w.x; Bs[lc+1][row]=w.y; Bs[lc+2][row]=w.z; Bs[lc+3][row]=w.w;
        }
        __syncthreads();
#pragma unroll
        for (int k = 0; k < 16; k++) {
            float4 a0 = *(const float4*)&As[k][ty*8];
            float4 a1 = *(const float4*)&As[k][ty*8+4];
            u64 ra2[8];
            ra2[0]=dup2(a0.x); ra2[1]=dup2(a0.y); ra2[2]=dup2(a0.z); ra2[3]=dup2(a0.w);
            ra2[4]=dup2(a1.x); ra2[5]=dup2(a1.y); ra2[6]=dup2(a1.z); ra2[7]=dup2(a1.w);
            ulonglong2 b0 = *(const ulonglong2*)&Bs[k][tx*8];
            ulonglong2 b1 = *(const ulonglong2*)&Bs[k][tx*8+4];
            u64 rb2[4] = { b0.x, b0.y, b1.x, b1.y };
#pragma unroll
            for (int i = 0; i < 8; i++)
#pragma unroll
                for (int j = 0; j < 4; j++)
                    fma2(acc2[i][j], ra2[i], rb2[j]);
        }
        __syncthreads();
    }

    if (blockIdx.z == 2) {
        // V: transposed bf16 hi/lo: idx = ((bh)*DH + d)*SS + s
#pragma unroll
        for (int i = 0; i < 8; i++) {
            int m = m0 + ty*8 + i;
            int b = m >> 11, s = m & 2047;
#pragma unroll
            for (int j2 = 0; j2 < 4; j2++) {
                float2 p = unpack2(acc2[i][j2]);
                int n = n0 + tx*8 + j2*2;
#pragma unroll
                for (int e = 0; e < 2; e++) {
                    int ne = n + e;
                    float x = (e == 0 ? p.x : p.y) + bias[ne];
                    __nv_bfloat16 hi = __float2bfloat16(x);
                    __nv_bfloat16 lo = __float2bfloat16(x - __bfloat162float(hi));
                    int h = ne >> 6, d = ne & 63;
                    size_t idx = ((size_t)((b*HH + h)*DH + d))*SS + s;
                    g_vth[idx] = hi;
                    g_vtl[idx] = lo;
                }
            }
        }
    } else {
        const float sc = (blockIdx.z == 0) ? 0.125f : 1.0f;
        __nv_bfloat16* oh = (blockIdx.z == 0) ? g_qh : g_kh;
        __nv_bfloat16* ol = (blockIdx.z == 0) ? g_ql : g_kl;
#pragma unroll
        for (int i = 0; i < 8; i++) {
            int m = m0 + ty*8 + i;
            int b = m >> 11, s = m & 2047;
#pragma unroll
            for (int j2 = 0; j2 < 4; j2++) {
                float2 p = unpack2(acc2[i][j2]);
                int n = n0 + tx*8 + j2*2;
#pragma unroll
                for (int e = 0; e < 2; e++) {
                    int ne = n + e;
                    float x = ((e == 0 ? p.x : p.y) + bias[ne]) * sc;
                    __nv_bfloat16 hi = __float2bfloat16(x);
                    __nv_bfloat16 lo = __float2bfloat16(x - __bfloat162float(hi));
                    int h = ne >> 6, d = ne & 63;
                    size_t idx = (((size_t)(b*HH + h)*SS + s) << 6) + d;
                    oh[idx] = hi;
                    ol[idx] = lo;
                }
            }
        }
    }
}

// ---------------------------------------------------------------------------
// K2 (mma.sync HMMA): scores = Qs K^T + res  (Q pre-scaled 1/8, bf16 3-split)
// ---------------------------------------------------------------------------
#define SMM_SMEM (4*16384)

__global__ __launch_bounds__(256) void scores_mma_kernel(
    const float* __restrict__ res, float* __restrict__ out_scores)
{
    extern __shared__ __align__(1024) char smem[];
    const int OF_QH = 0, OF_QL = 16384, OF_KH = 32768, OF_KL = 49152;

    const int tid = threadIdx.x;
    const int bh = blockIdx.z;
    const int m0 = blockIdx.y * 128;
    const int n0 = blockIdx.x * 128;
    const uint32_t sb = smem_u32(smem);

    {
        const uint4* sqh = (const uint4*)(g_qh + (size_t)(bh*SS + m0)*DH);
        const uint4* sql = (const uint4*)(g_ql + (size_t)(bh*SS + m0)*DH);
        const uint4* skh = (const uint4*)(g_kh + (size_t)(bh*SS + n0)*DH);
        const uint4* skl = (const uint4*)(g_kl + (size_t)(bh*SS + n0)*DH);
        for (int idx = tid; idx < 1024; idx += 256) {
            uint32_t off = (uint32_t)idx * 16;
            uint32_t sw = off ^ ((off >> 3) & 0x70);
            *(uint4*)(smem + OF_QH + sw) = sqh[idx];
            *(uint4*)(smem + OF_QL + sw) = sql[idx];
            *(uint4*)(smem + OF_KH + sw) = skh[idx];
            *(uint4*)(smem + OF_KL + sw) = skl[idx];
        }
    }
    __syncthreads();

    const int wid = tid >> 5, lane = tid & 31;
    const int wm = wid & 3, wn = wid >> 2;
    const int mw0 = wm * 32;
    const int nw0 = wn * 64;

    float acc[2][8][4];
#pragma unroll
    for (int i = 0; i < 2; i++)
#pragma unroll
        for (int j = 0; j < 8; j++)
#pragma unroll
            for (int q = 0; q < 4; q++) acc[i][j][q] = 0.f;

    const int lrow = lane & 15;
    const int lkh  = (lane >> 4) * 16;

    const int aoffs[3] = { OF_QH, OF_QH, OF_QL };
    const int boffs[3] = { OF_KH, OF_KL, OF_KH };

#pragma unroll
    for (int s = 0; s < 3; s++) {
        const int aOff = aoffs[s], bOff = boffs[s];
#pragma unroll
        for (int ks = 0; ks < 4; ks++) {
            const uint32_t colb = (uint32_t)(ks*32 + lkh);
            uint32_t af[2][4];
#pragma unroll
            for (int mi = 0; mi < 2; mi++) {
                uint32_t off = (uint32_t)(mw0 + mi*16 + lrow) * 128 + colb;
                uint32_t sw = off ^ ((off >> 3) & 0x70);
                ldmx4(af[mi], sb + aOff + sw);
            }
            uint32_t bf[4][4];
#pragma unroll
            for (int nj = 0; nj < 4; nj++) {
                uint32_t off = (uint32_t)(nw0 + nj*16 + lrow) * 128 + colb;
                uint32_t sw = off ^ ((off >> 3) & 0x70);
                ldmx4(bf[nj], sb + bOff + sw);
            }
#pragma unroll
            for (int mi = 0; mi < 2; mi++)
#pragma unroll
                for (int nj = 0; nj < 4; nj++) {
                    mma16816(acc[mi][nj*2+0], af[mi], bf[nj][0], bf[nj][2]);
                    mma16816(acc[mi][nj*2+1], af[mi], bf[nj][1], bf[nj][3]);
                }
        }
    }

    const float* R = res + (size_t)bh * SS * SS;
    float* O = out_scores + (size_t)bh * SS * SS;
#pragma unroll
    for (int mi = 0; mi < 2; mi++) {
#pragma unroll
        for (int half = 0; half < 2; half++) {
            int m = m0 + mw0 + mi*16 + (lane >> 2) + half*8;
            const float* rrow = R + (size_t)m * SS + n0 + nw0 + (lane & 3)*2;
            float* orow = O + (size_t)m * SS + n0 + nw0 + (lane & 3)*2;
#pragma unroll
            for (int nj = 0; nj < 8; nj++) {
                float2 r = *(const float2*)(rrow + nj*8);
                float2 o;
                o.x = acc[mi][nj][half*2+0] + r.x;
                o.y = acc[mi][nj][half*2+1] + r.y;
                *(float2*)(orow + nj*8) = o;
            }
        }
    }
}

// ---------------------------------------------------------------------------
// K3: per-row softmax stats over (scores + mask): rowmax m, sum l
// ---------------------------------------------------------------------------
__device__ __forceinline__ float warpRedMax(float v) {
#pragma unroll
    for (int o = 16; o > 0; o >>= 1) v = fmaxf(v, __shfl_xor_sync(0xffffffffu, v, o));
    return v;
}
__device__ __forceinline__ float warpRedSum(float v) {
#pragma unroll
    for (int o = 16; o > 0; o >>= 1) v += __shfl_xor_sync(0xffffffffu, v, o);
    return v;
}

__global__ __launch_bounds__(256) void softmax_stats_kernel(
    const float* __restrict__ scores, const float* __restrict__ mask)
{
    const int tid = threadIdx.x;
    __shared__ float red[8];

#pragma unroll
    for (int rr = 0; rr < 4; rr++) {
        const int row = blockIdx.x * 4 + rr;
        const int b = row / (HH*SS);
        const float* sr = scores + (size_t)row * SS;
        const float* mr = mask + (size_t)b * SS;

        float vals[8];
        float lm = -CUDART_INF_F;
#pragma unroll
        for (int i = 0; i < 8; i++) {
            int c = tid + i*256;
            float v = sr[c] + mr[c];
            vals[i] = v;
            lm = fmaxf(lm, v);
        }

        float wm = warpRedMax(lm);
        if ((tid & 31) == 0) red[tid >> 5] = wm;
        __syncthreads();
        float bm = red[0];
#pragma unroll
        for (int w = 1; w < 8; w++) bm = fmaxf(bm, red[w]);

        float ls = 0.f;
#pragma unroll
        for (int i = 0; i < 8; i++) ls += __expf(vals[i] - bm);
        __syncthreads();
        float ws = warpRedSum(ls);
        if ((tid & 31) == 0) red[tid >> 5] = ws;
        __syncthreads();
        if (tid == 0) {
            float s = 0.f;
#pragma unroll
            for (int w = 0; w < 8; w++) s += red[w];
            g_m[row] = bm;
            g_l[row] = s;
        }
        __syncthreads();
    }
}

// ---------------------------------------------------------------------------
// K4 (mma.sync HMMA, v2): ctx = softmax(scores+mask) @ V.
// Per CTA: 128(m) x 64(n=DH), K=2048 in 32 chunks of 64.
// 8 warps each own 16 m-rows x full n (no k-split): acc = 32 regs.
// __launch_bounds__(256,2) -> 2 CTAs/SM, 16 warps resident.
// smem/CTA: PH 16K + PL 16K + VH 8K + VL 8K + stats 1K = 49.25 KB.
// ---------------------------------------------------------------------------
#define PV_OF_PH 0
#define PV_OF_PL 16384
#define PV_OF_VH 32768
#define PV_OF_VL 40960
#define PV_OF_MS 49152
#define PV_OF_RL (49152 + 512)
#define PV_SMEM  (49152 + 1024)

__global__ __launch_bounds__(256, 2) void pv_mma_kernel(
    const float* __restrict__ scores, const float* __restrict__ mask,
    float* __restrict__ ctx)
{
    extern __shared__ __align__(1024) char smem[];
    const int tid = threadIdx.x;
    const int bh = blockIdx.z;
    const int b = bh / HH, h = bh % HH;
    const int m0 = blockIdx.y * 128;
    const uint32_t sb = smem_u32(smem);

    float* ms  = (float*)(smem + PV_OF_MS);
    float* rls = (float*)(smem + PV_OF_RL);
    if (tid < 128) {
        int r = bh*SS + m0 + tid;
        ms[tid]  = g_m[r];
        rls[tid] = 1.0f / g_l[r];
    }
    __syncthreads();

    const int wid = tid >> 5, lane = tid & 31;
    const int mw0 = wid * 16;          // warp's 16 m-rows
    const int lrow = lane & 15;
    const int lkh  = (lane >> 4) * 16;

    // P-gen mapping: row pr (0..127), col-half hf (32 cols each)
    const int pr = tid >> 1;
    const int hf = tid & 1;
    const float mrow = ms[pr];
    const float* srow = scores + (size_t)bh*SS*SS + (size_t)(m0 + pr)*SS;
    const float* mk_row = mask + (size_t)b*SS;

    float acc[8][4];
#pragma unroll
    for (int j = 0; j < 8; j++)
#pragma unroll
        for (int q = 0; q < 4; q++) acc[j][q] = 0.f;

    const __nv_bfloat16* vth = g_vth + (size_t)(bh*DH)*SS;
    const __nv_bfloat16* vtl = g_vtl + (size_t)(bh*DH)*SS;

    for (int kc0 = 0; kc0 < SS; kc0 += 64) {
        // --- V subtile: [d][k] 64x64 bf16 hi/lo, 128B rows, SW128 swizzle
        {
            int i = tid;            // 256 threads x 2 iters = 512 uint4
#pragma unroll
            for (int it = 0; it < 2; it++, i += 256) {
                int d = i >> 3, u = i & 7;
                size_t g = (size_t)d * SS + kc0 + u*8;
                uint32_t off = (uint32_t)(d*128 + u*16);
                uint32_t sw = off ^ ((off >> 3) & 0x70);
                *(uint4*)(smem + PV_OF_VH + sw) = *(const uint4*)(vth + g);
                *(uint4*)(smem + PV_OF_VL + sw) = *(const uint4*)(vtl + g);
            }
        }

        // --- P tile: row pr, cols kc0 + hf*32 + [0..32): 4 uint4 hi + 4 lo
        {
            const float* sc = srow + kc0 + hf*32;
            const float* mk = mk_row + kc0 + hf*32;
#pragma unroll
            for (int u = 0; u < 4; u++) {
                float4 s0 = *(const float4*)(sc + u*8);
                float4 s1 = *(const float4*)(sc + u*8 + 4);
                float4 k0v = *(const float4*)(mk + u*8);
                float4 k1v = *(const float4*)(mk + u*8 + 4);
                float e[8];
                e[0] = __expf(s0.x + k0v.x - mrow);
                e[1] = __expf(s0.y + k0v.y - mrow);
                e[2] = __expf(s0.z + k0v.z - mrow);
                e[3] = __expf(s0.w + k0v.w - mrow);
                e[4] = __expf(s1.x + k1v.x - mrow);
                e[5] = __expf(s1.y + k1v.y - mrow);
                e[6] = __expf(s1.z + k1v.z - mrow);
                e[7] = __expf(s1.w + k1v.w - mrow);
                __nv_bfloat16 hi[8]; float lo[8];
#pragma unroll
                for (int t = 0; t < 8; t++) {
                    hi[t] = __float2bfloat16(e[t]);
                    lo[t] = e[t] - __bfloat162float(hi[t]);
                }
                uint4 hp, lp;
                hp.x = pack_bf2(hi[0], hi[1]); hp.y = pack_bf2(hi[2], hi[3]);
                hp.z = pack_bf2(hi[4], hi[5]); hp.w = pack_bf2(hi[6], hi[7]);
                lp.x = pack_bf2(__float2bfloat16(lo[0]), __float2bfloat16(lo[1]));
                lp.y = pack_bf2(__float2bfloat16(lo[2]), __float2bfloat16(lo[3]));
                lp.z = pack_bf2(__float2bfloat16(lo[4]), __float2bfloat16(lo[5]));
                lp.w = pack_bf2(__float2bfloat16(lo[6]), __float2bfloat16(lo[7]));
                uint32_t off = (uint32_t)(pr*128 + hf*64 + u*16);
                uint32_t sw = off ^ ((off >> 3) & 0x70);
                *(uint4*)(smem + PV_OF_PH + sw) = hp;
                *(uint4*)(smem + PV_OF_PL + sw) = lp;
            }
        }
        __syncthreads();

        // --- HMMA: warp wid on rows [mw0, mw0+16), all n=64, k=64
#pragma unroll
        for (int ks = 0; ks < 4; ks++) {
            const uint32_t colb = (uint32_t)(ks*32 + lkh);
            uint32_t ah[4], al[4];
            {
                uint32_t off = (uint32_t)(mw0 + lrow) * 128 + colb;
                uint32_t sw = off ^ ((off >> 3) & 0x70);
                ldmx4(ah, sb + PV_OF_PH + sw);
                ldmx4(al, sb + PV_OF_PL + sw);
            }
            uint32_t bhf[4][4], blf[4][4];
#pragma unroll
            for (int nj = 0; nj < 4; nj++) {
                uint32_t off = (uint32_t)(nj*16 + lrow) * 128 + colb;
                uint32_t sw = off ^ ((off >> 3) & 0x70);
                ldmx4(bhf[nj], sb + PV_OF_VH + sw);
                ldmx4(blf[nj], sb + PV_OF_VL + sw);
            }
#pragma unroll
            for (int nj = 0; nj < 4; nj++) {
                mma16816(acc[nj*2+0], ah, bhf[nj][0], bhf[nj][2]);
                mma16816(acc[nj*2+1], ah, bhf[nj][1], bhf[nj][3]);
                mma16816(acc[nj*2+0], ah, blf[nj][0], blf[nj][2]);
                mma16816(acc[nj*2+1], ah, blf[nj][1], blf[nj][3]);
                mma16816(acc[nj*2+0], al, bhf[nj][0], bhf[nj][2]);
                mma16816(acc[nj*2+1], al, bhf[nj][1], bhf[nj][3]);
            }
        }
        __syncthreads();
    }

    // --- epilogue: scale 1/l, write ctx
#pragma unroll
    for (int half = 0; half < 2; half++) {
        int lm = mw0 + (lane >> 2) + half*8;
        int m = m0 + lm;
        float rl = rls[lm];
        float* orow = ctx + ((size_t)b*SS + m)*DD + h*DH + (lane & 3)*2;
#pragma unroll
        for (int nj = 0; nj < 8; nj++) {
            float2 o;
            o.x = acc[nj][half*2+0] * rl;
            o.y = acc[nj][half*2+1] * rl;
            *(float2*)(orow + nj*8) = o;
        }
    }
}

// ---------------------------------------------------------------------------
extern "C" void kernel_launch(void* const* d_in, const int* in_sizes, int n_in,
                              void* d_out, int out_size)
{
    const float* hid  = (const float*)d_in[0];
    const float* mask = (const float*)d_in[1];
    const float* res  = (const float*)d_in[2];
    const float* Wq = (const float*)d_in[3];
    const float* bq = (const float*)d_in[4];
    const float* Wk = (const float*)d_in[5];
    const float* bk = (const float*)d_in[6];
    const float* Wv = (const float*)d_in[7];
    const float* bv = (const float*)d_in[8];

    float* out_ctx    = (float*)d_out;
    float* out_scores = (float*)d_out + (size_t)BB*SS*DD;

    cudaFuncSetAttribute(scores_mma_kernel,
                         cudaFuncAttributeMaxDynamicSharedMemorySize, SMM_SMEM);
    cudaFuncSetAttribute(pv_mma_kernel,
                         cudaFuncAttributeMaxDynamicSharedMemorySize, PV_SMEM);

    qkv_kernel<<<dim3(DD/128, (BB*SS)/128, 3), 256>>>(hid, Wq, bq, Wk, bk, Wv, bv);
    scores_mma_kernel<<<dim3(SS/128, SS/128, BH), 256, SMM_SMEM>>>(res, out_scores);
    softmax_stats_kernel<<<dim3(ROWS_TOTAL/4), 256>>>(out_scores, mask);
    pv_mma_kernel<<<dim3(1, SS/128, BH), 256, PV_SMEM>>>(out_scores, mask, out_ctx);
}

// round 11
// speedup vs baseline: 1.4359x; 1.3593x over previous
#include <cuda_runtime.h>
#include <cuda_bf16.h>
#include <math_constants.h>
#include <cstdint>

// Problem dims (fixed)
#define BB 2
#define SS 2048
#define DD 768
#define HH 12
#define DH 64
#define BH (BB*HH)          // 24
#define ROWS_TOTAL (BB*HH*SS) // 49152

typedef unsigned long long u64;

// ---- packed f32x2 helpers (Blackwell FFMA2 path) --------------------------
__device__ __forceinline__ u64 dup2(float v) {
    u64 r; asm("mov.b64 %0, {%1, %1};" : "=l"(r) : "f"(v)); return r;
}
__device__ __forceinline__ void fma2(u64& d, u64 a, u64 b) {
    asm("fma.rn.f32x2 %0, %1, %2, %0;" : "+l"(d) : "l"(a), "l"(b));
}
__device__ __forceinline__ float2 unpack2(u64 v) {
    float2 r; asm("mov.b64 {%0, %1}, %2;" : "=f"(r.x), "=f"(r.y) : "l"(v)); return r;
}

// Scratch (device globals: sanctioned scratch mechanism)
__device__ __nv_bfloat16 g_qh[BB*HH*SS*DH];  // Q*0.125 split-hi
__device__ __nv_bfloat16 g_ql[BB*HH*SS*DH];  // Q*0.125 split-lo
__device__ __nv_bfloat16 g_kh[BB*HH*SS*DH];
__device__ __nv_bfloat16 g_kl[BB*HH*SS*DH];
__device__ __nv_bfloat16 g_vth[BB*HH*DH*SS]; // V^T [bh][d][s] split-hi
__device__ __nv_bfloat16 g_vtl[BB*HH*DH*SS]; // V^T split-lo

__device__ __forceinline__ uint32_t smem_u32(const void* p) {
    uint32_t a;
    asm("{ .reg .u64 t; cvta.to.shared.u64 t, %1; cvt.u32.u64 %0, t; }" : "=r"(a) : "l"(p));
    return a;
}
__device__ __forceinline__ void ldmx4(uint32_t* r, uint32_t addr) {
    asm volatile("ldmatrix.sync.aligned.m8n8.x4.shared.b16 {%0,%1,%2,%3}, [%4];"
        : "=r"(r[0]), "=r"(r[1]), "=r"(r[2]), "=r"(r[3]) : "r"(addr));
}
__device__ __forceinline__ void mma16816(float* c, const uint32_t* a, uint32_t b0, uint32_t b1) {
    asm volatile(
        "mma.sync.aligned.m16n8k16.row.col.f32.bf16.bf16.f32 "
        "{%0,%1,%2,%3},{%4,%5,%6,%7},{%8,%9},{%0,%1,%2,%3};"
        : "+f"(c[0]), "+f"(c[1]), "+f"(c[2]), "+f"(c[3])
        : "r"(a[0]), "r"(a[1]), "r"(a[2]), "r"(a[3]), "r"(b0), "r"(b1));
}
__device__ __forceinline__ uint32_t pack_bf2(__nv_bfloat16 a, __nv_bfloat16 b) {
    return (uint32_t)__bfloat16_as_ushort(a) | ((uint32_t)__bfloat16_as_ushort(b) << 16);
}
__device__ __forceinline__ uint32_t swz(uint32_t off) {
    return off ^ ((off >> 3) & 0x70);
}

// ---------------------------------------------------------------------------
// K1: QKV projection. q,k as bf16 hi/lo splits (q pre-scaled 0.125);
// v as bf16 hi/lo splits in TRANSPOSED layout [bh][d][s].
// ---------------------------------------------------------------------------
__global__ __launch_bounds__(256) void qkv_kernel(
    const float* __restrict__ hid,
    const float* __restrict__ Wq, const float* __restrict__ bq,
    const float* __restrict__ Wk, const float* __restrict__ bk,
    const float* __restrict__ Wv, const float* __restrict__ bv)
{
    const float* W; const float* bias;
    if (blockIdx.z == 0)      { W = Wq; bias = bq; }
    else if (blockIdx.z == 1) { W = Wk; bias = bk; }
    else                      { W = Wv; bias = bv; }

    __shared__ __align__(16) float As[16][128+4];
    __shared__ __align__(16) float Bs[16][128+4];

    const int tid = threadIdx.x;
    const int m0 = blockIdx.y * 128;
    const int n0 = blockIdx.x * 128;

    const int lr = tid >> 2;          // 0..63
    const int lc = (tid & 3) << 2;    // 0,4,8,12
    const int ty = tid >> 4;          // 0..15
    const int tx = tid & 15;          // 0..15

    u64 acc2[8][4];                   // [i][j-pair]
#pragma unroll
    for (int i = 0; i < 8; i++)
#pragma unroll
        for (int j = 0; j < 4; j++) acc2[i][j] = 0ull;

    for (int k0 = 0; k0 < DD; k0 += 16) {
#pragma unroll
        for (int r = 0; r < 2; r++) {
            int row = lr + r*64;
            float4 a = *(const float4*)(hid + (size_t)(m0+row)*DD + k0 + lc);
            As[lc+0][row]=a.x; As[lc+1][row]=a.y; As[lc+2][row]=a.z; As[lc+3][row]=a.w;
            float4 w = *(const float4*)(W + (size_t)(n0+row)*DD + k0 + lc);
            Bs[lc+0][row]=w.x; Bs[lc+1][row]=w.y; Bs[lc+2][row]=w.z; Bs[lc+3][row]=w.w;
        }
        __syncthreads();
#pragma unroll
        for (int k = 0; k < 16; k++) {
            float4 a0 = *(const float4*)&As[k][ty*8];
            float4 a1 = *(const float4*)&As[k][ty*8+4];
            u64 ra2[8];
            ra2[0]=dup2(a0.x); ra2[1]=dup2(a0.y); ra2[2]=dup2(a0.z); ra2[3]=dup2(a0.w);
            ra2[4]=dup2(a1.x); ra2[5]=dup2(a1.y); ra2[6]=dup2(a1.z); ra2[7]=dup2(a1.w);
            ulonglong2 b0 = *(const ulonglong2*)&Bs[k][tx*8];
            ulonglong2 b1 = *(const ulonglong2*)&Bs[k][tx*8+4];
            u64 rb2[4] = { b0.x, b0.y, b1.x, b1.y };
#pragma unroll
            for (int i = 0; i < 8; i++)
#pragma unroll
                for (int j = 0; j < 4; j++)
                    fma2(acc2[i][j], ra2[i], rb2[j]);
        }
        __syncthreads();
    }

    if (blockIdx.z == 2) {
        // V: transposed bf16 hi/lo: idx = ((bh)*DH + d)*SS + s
#pragma unroll
        for (int i = 0; i < 8; i++) {
            int m = m0 + ty*8 + i;
            int b = m >> 11, s = m & 2047;
#pragma unroll
            for (int j2 = 0; j2 < 4; j2++) {
                float2 p = unpack2(acc2[i][j2]);
                int n = n0 + tx*8 + j2*2;
#pragma unroll
                for (int e = 0; e < 2; e++) {
                    int ne = n + e;
                    float x = (e == 0 ? p.x : p.y) + bias[ne];
                    __nv_bfloat16 hi = __float2bfloat16(x);
                    __nv_bfloat16 lo = __float2bfloat16(x - __bfloat162float(hi));
                    int h = ne >> 6, d = ne & 63;
                    size_t idx = ((size_t)((b*HH + h)*DH + d))*SS + s;
                    g_vth[idx] = hi;
                    g_vtl[idx] = lo;
                }
            }
        }
    } else {
        const float sc = (blockIdx.z == 0) ? 0.125f : 1.0f;
        __nv_bfloat16* oh = (blockIdx.z == 0) ? g_qh : g_kh;
        __nv_bfloat16* ol = (blockIdx.z == 0) ? g_ql : g_kl;
#pragma unroll
        for (int i = 0; i < 8; i++) {
            int m = m0 + ty*8 + i;
            int b = m >> 11, s = m & 2047;
#pragma unroll
            for (int j2 = 0; j2 < 4; j2++) {
                float2 p = unpack2(acc2[i][j2]);
                int n = n0 + tx*8 + j2*2;
#pragma unroll
                for (int e = 0; e < 2; e++) {
                    int ne = n + e;
                    float x = ((e == 0 ? p.x : p.y) + bias[ne]) * sc;
                    __nv_bfloat16 hi = __float2bfloat16(x);
                    __nv_bfloat16 lo = __float2bfloat16(x - __bfloat162float(hi));
                    int h = ne >> 6, d = ne & 63;
                    size_t idx = (((size_t)(b*HH + h)*SS + s) << 6) + d;
                    oh[idx] = hi;
                    ol[idx] = lo;
                }
            }
        }
    }
}

// ---------------------------------------------------------------------------
// K2 (fused flash attention, mma.sync HMMA bf16 3-split):
//   S = Qs K^T;  scores_out = S + res;  online softmax over (S+res+mask);
//   ctx = (softmax) @ V.  One pass over K; scores written once, never re-read.
// Per CTA: 64 m-rows (4 warps x 16 rows), chunks of 128 n-cols.
// smem: Qstage 16K | KH 16K | KL 16K | VH 16K (2x8K subs) | VL 16K | mask 512B
// ---------------------------------------------------------------------------
#define FA_OF_QS 0
#define FA_OF_KH 16384
#define FA_OF_KL 32768
#define FA_OF_VH 49152
#define FA_OF_VL 65536
#define FA_OF_MK 81920
#define FA_SMEM  (81920 + 512)

__global__ __launch_bounds__(128, 2) void fused_attn_kernel(
    const float* __restrict__ res, const float* __restrict__ mask,
    float* __restrict__ out_scores, float* __restrict__ ctx)
{
    extern __shared__ __align__(1024) char smem[];
    const int tid = threadIdx.x;
    const int bh = blockIdx.y;
    const int b = bh / HH, h = bh % HH;
    const int m0 = blockIdx.x * 64;
    const uint32_t sb = smem_u32(smem);

    const int wid = tid >> 5, lane = tid & 31;
    const int lrow = lane & 15;
    const int lkh  = (lane >> 4) * 16;
    const int cbase = (lane & 3) * 2;
    const int wrow = wid * 16;              // warp's row base within 64-tile

    float* masksm = (float*)(smem + FA_OF_MK);

    // --- Stage Q hi/lo (64 rows x 64 k) and load resident A-frags ---
    {
        const uint4* sqh = (const uint4*)(g_qh + (size_t)(bh*SS + m0)*DH);
        const uint4* sql = (const uint4*)(g_ql + (size_t)(bh*SS + m0)*DH);
        for (int i = tid; i < 512; i += 128) {
            uint32_t sw = swz((uint32_t)i * 16);
            *(uint4*)(smem + FA_OF_QS + sw) = sqh[i];
            *(uint4*)(smem + FA_OF_QS + 8192 + sw) = sql[i];
        }
    }
    __syncthreads();

    uint32_t qa_h[4][4], qa_l[4][4];
#pragma unroll
    for (int t = 0; t < 4; t++) {
        uint32_t sw = swz((uint32_t)(wrow + lrow) * 128 + t*32 + lkh);
        ldmx4(qa_h[t], sb + FA_OF_QS + sw);
        ldmx4(qa_l[t], sb + FA_OF_QS + 8192 + sw);
    }

    // --- running stats + O accumulator ---
    float mrun0 = -CUDART_INF_F, mrun1 = -CUDART_INF_F;
    float lrun0 = 0.f, lrun1 = 0.f;
    float O[8][4];
#pragma unroll
    for (int j = 0; j < 8; j++)
#pragma unroll
        for (int q = 0; q < 4; q++) O[j][q] = 0.f;

    const int r0 = wrow + (lane >> 2);      // thread's row A (0..63)
    const int r1 = r0 + 8;                  // row B
    const float* Rrow0 = res + (size_t)bh*SS*SS + (size_t)(m0 + r0)*SS;
    const float* Rrow1 = res + (size_t)bh*SS*SS + (size_t)(m0 + r1)*SS;
    float* Srow0 = out_scores + (size_t)bh*SS*SS + (size_t)(m0 + r0)*SS;
    float* Srow1 = out_scores + (size_t)bh*SS*SS + (size_t)(m0 + r1)*SS;
    const __nv_bfloat16* vth = g_vth + (size_t)(bh*DH)*SS;
    const __nv_bfloat16* vtl = g_vtl + (size_t)(bh*DH)*SS;
    const __nv_bfloat16* kph = g_kh + (size_t)(bh*SS)*DH;
    const __nv_bfloat16* kpl = g_kl + (size_t)(bh*SS)*DH;

    for (int n0 = 0; n0 < SS; n0 += 128) {
        // ---- stage K (128 x 64) hi/lo ----
        {
            const uint4* skh = (const uint4*)(kph + (size_t)n0*DH);
            const uint4* skl = (const uint4*)(kpl + (size_t)n0*DH);
            for (int i = tid; i < 1024; i += 128) {
                uint32_t sw = swz((uint32_t)i * 16);
                *(uint4*)(smem + FA_OF_KH + sw) = skh[i];
                *(uint4*)(smem + FA_OF_KL + sw) = skl[i];
            }
        }
        // ---- stage V^T subtiles: [sub][d 0..63][s 64] hi/lo ----
        for (int i = tid; i < 1024; i += 128) {
            int sub = i >> 9, rem = i & 511;
            int d = rem >> 3, u = rem & 7;
            size_t g = (size_t)d * SS + n0 + sub*64 + u*8;
            uint32_t sw = swz((uint32_t)(d*128 + u*16));
            *(uint4*)(smem + FA_OF_VH + sub*8192 + sw) = *(const uint4*)(vth + g);
            *(uint4*)(smem + FA_OF_VL + sub*8192 + sw) = *(const uint4*)(vtl + g);
        }
        masksm[tid] = mask[(size_t)b*SS + n0 + tid];
        __syncthreads();

        // ---- S = Qs K^T (3-split) ----
        float sfr[16][4];
#pragma unroll
        for (int j = 0; j < 16; j++)
#pragma unroll
            for (int q = 0; q < 4; q++) sfr[j][q] = 0.f;

#pragma unroll
        for (int kt = 0; kt < 4; kt++) {
            const uint32_t colb = (uint32_t)(kt*32 + lkh);
#pragma unroll
            for (int j = 0; j < 8; j++) {
                uint32_t sw = swz((uint32_t)(j*16 + lrow) * 128 + colb);
                uint32_t bb[4];
                ldmx4(bb, sb + FA_OF_KH + sw);
                mma16816(sfr[2*j+0], qa_h[kt], bb[0], bb[2]);
                mma16816(sfr[2*j+1], qa_h[kt], bb[1], bb[3]);
                mma16816(sfr[2*j+0], qa_l[kt], bb[0], bb[2]);
                mma16816(sfr[2*j+1], qa_l[kt], bb[1], bb[3]);
                ldmx4(bb, sb + FA_OF_KL + sw);
                mma16816(sfr[2*j+0], qa_h[kt], bb[0], bb[2]);
                mma16816(sfr[2*j+1], qa_h[kt], bb[1], bb[3]);
            }
        }

        // ---- +res, write scores, +mask, tile max ----
        float tmax0 = -CUDART_INF_F, tmax1 = -CUDART_INF_F;
#pragma unroll
        for (int j = 0; j < 16; j++) {
            int col = n0 + j*8 + cbase;
            float2 rv0 = *(const float2*)(Rrow0 + col);
            float2 rv1 = *(const float2*)(Rrow1 + col);
            float s00 = sfr[j][0] + rv0.x, s01 = sfr[j][1] + rv0.y;
            float s10 = sfr[j][2] + rv1.x, s11 = sfr[j][3] + rv1.y;
            *(float2*)(Srow0 + col) = make_float2(s00, s01);
            *(float2*)(Srow1 + col) = make_float2(s10, s11);
            float mk0 = masksm[j*8 + cbase], mk1 = masksm[j*8 + cbase + 1];
            s00 += mk0; s01 += mk1; s10 += mk0; s11 += mk1;
            sfr[j][0] = s00; sfr[j][1] = s01; sfr[j][2] = s10; sfr[j][3] = s11;
            tmax0 = fmaxf(tmax0, fmaxf(s00, s01));
            tmax1 = fmaxf(tmax1, fmaxf(s10, s11));
        }
        tmax0 = fmaxf(tmax0, __shfl_xor_sync(0xffffffffu, tmax0, 1));
        tmax0 = fmaxf(tmax0, __shfl_xor_sync(0xffffffffu, tmax0, 2));
        tmax1 = fmaxf(tmax1, __shfl_xor_sync(0xffffffffu, tmax1, 1));
        tmax1 = fmaxf(tmax1, __shfl_xor_sync(0xffffffffu, tmax1, 2));

        // ---- online rescale ----
        float mnew0 = fmaxf(mrun0, tmax0);
        float mnew1 = fmaxf(mrun1, tmax1);
        float sc0 = __expf(mrun0 - mnew0);
        float sc1 = __expf(mrun1 - mnew1);
        mrun0 = mnew0; mrun1 = mnew1;
        lrun0 *= sc0; lrun1 *= sc1;
#pragma unroll
        for (int j = 0; j < 8; j++) {
            O[j][0] *= sc0; O[j][1] *= sc0;
            O[j][2] *= sc1; O[j][3] *= sc1;
        }

        // ---- exp + pack P into A-frags (hi/lo) ----
        uint32_t pah[8][4], pal[8][4];
#pragma unroll
        for (int j = 0; j < 16; j++) {
            float e0 = __expf(sfr[j][0] - mnew0);
            float e1 = __expf(sfr[j][1] - mnew0);
            float e2 = __expf(sfr[j][2] - mnew1);
            float e3 = __expf(sfr[j][3] - mnew1);
            lrun0 += e0 + e1;
            lrun1 += e2 + e3;
            __nv_bfloat16 h0 = __float2bfloat16(e0), h1 = __float2bfloat16(e1);
            __nv_bfloat16 h2 = __float2bfloat16(e2), h3 = __float2bfloat16(e3);
            int t = j >> 1, odd = j & 1;
            pah[t][odd*2+0] = pack_bf2(h0, h1);
            pah[t][odd*2+1] = pack_bf2(h2, h3);
            pal[t][odd*2+0] = pack_bf2(__float2bfloat16(e0 - __bfloat162float(h0)),
                                       __float2bfloat16(e1 - __bfloat162float(h1)));
            pal[t][odd*2+1] = pack_bf2(__float2bfloat16(e2 - __bfloat162float(h2)),
                                       __float2bfloat16(e3 - __bfloat162float(h3)));
        }

        // ---- O += P V (3-split) ----
#pragma unroll
        for (int t = 0; t < 8; t++) {
            int sub = t >> 2, ks = t & 3;
            const uint32_t colb = (uint32_t)(ks*32 + lkh);
#pragma unroll
            for (int nj = 0; nj < 4; nj++) {
                uint32_t sw = swz((uint32_t)(nj*16 + lrow) * 128 + colb);
                uint32_t vv[4];
                ldmx4(vv, sb + FA_OF_VH + sub*8192 + sw);
                mma16816(O[2*nj+0], pah[t], vv[0], vv[2]);
                mma16816(O[2*nj+1], pah[t], vv[1], vv[3]);
                mma16816(O[2*nj+0], pal[t], vv[0], vv[2]);
                mma16816(O[2*nj+1], pal[t], vv[1], vv[3]);
                ldmx4(vv, sb + FA_OF_VL + sub*8192 + sw);
                mma16816(O[2*nj+0], pah[t], vv[0], vv[2]);
                mma16816(O[2*nj+1], pah[t], vv[1], vv[3]);
            }
        }
        __syncthreads();
    }

    // ---- finalize: reduce l across 4-lane group, scale, write ctx ----
    lrun0 += __shfl_xor_sync(0xffffffffu, lrun0, 1);
    lrun0 += __shfl_xor_sync(0xffffffffu, lrun0, 2);
    lrun1 += __shfl_xor_sync(0xffffffffu, lrun1, 1);
    lrun1 += __shfl_xor_sync(0xffffffffu, lrun1, 2);
    float rl0 = 1.0f / lrun0;
    float rl1 = 1.0f / lrun1;

    float* c0 = ctx + ((size_t)b*SS + m0 + r0)*DD + h*DH + cbase;
    float* c1 = ctx + ((size_t)b*SS + m0 + r1)*DD + h*DH + cbase;
#pragma unroll
    for (int nj = 0; nj < 8; nj++) {
        *(float2*)(c0 + nj*8) = make_float2(O[nj][0]*rl0, O[nj][1]*rl0);
        *(float2*)(c1 + nj*8) = make_float2(O[nj][2]*rl1, O[nj][3]*rl1);
    }
}

// ---------------------------------------------------------------------------
extern "C" void kernel_launch(void* const* d_in, const int* in_sizes, int n_in,
                              void* d_out, int out_size)
{
    const float* hid  = (const float*)d_in[0];
    const float* mask = (const float*)d_in[1];
    const float* res  = (const float*)d_in[2];
    const float* Wq = (const float*)d_in[3];
    const float* bq = (const float*)d_in[4];
    const float* Wk = (const float*)d_in[5];
    const float* bk = (const float*)d_in[6];
    const float* Wv = (const float*)d_in[7];
    const float* bv = (const float*)d_in[8];

    float* out_ctx    = (float*)d_out;
    float* out_scores = (float*)d_out + (size_t)BB*SS*DD;

    cudaFuncSetAttribute(fused_attn_kernel,
                         cudaFuncAttributeMaxDynamicSharedMemorySize, FA_SMEM);

    qkv_kernel<<<dim3(DD/128, (BB*SS)/128, 3), 256>>>(hid, Wq, bq, Wk, bk, Wv, bv);
    fused_attn_kernel<<<dim3(SS/64, BH), 128, FA_SMEM>>>(res, mask, out_scores, out_ctx);
}

// round 12
// speedup vs baseline: 1.8034x; 1.2559x over previous
#include <cuda_runtime.h>
#include <cuda_bf16.h>
#include <math_constants.h>
#include <cstdint>

// Problem dims (fixed)
#define BB 2
#define SS 2048
#define DD 768
#define HH 12
#define DH 64
#define BH (BB*HH)          // 24
#define ROWS_TOTAL (BB*HH*SS) // 49152

typedef unsigned long long u64;

// Scratch (device globals: sanctioned scratch mechanism)
__device__ __nv_bfloat16 g_hh[BB*SS*DD];     // hidden split-hi
__device__ __nv_bfloat16 g_hl[BB*SS*DD];     // hidden split-lo
__device__ __nv_bfloat16 g_wh[3*DD*DD];      // Wq|Wk|Wv split-hi
__device__ __nv_bfloat16 g_wl[3*DD*DD];      // Wq|Wk|Wv split-lo
__device__ __nv_bfloat16 g_qh[BB*HH*SS*DH];  // Q*0.125 split-hi
__device__ __nv_bfloat16 g_ql[BB*HH*SS*DH];  // Q*0.125 split-lo
__device__ __nv_bfloat16 g_kh[BB*HH*SS*DH];
__device__ __nv_bfloat16 g_kl[BB*HH*SS*DH];
__device__ __nv_bfloat16 g_vth[BB*HH*DH*SS]; // V^T [bh][d][s] split-hi
__device__ __nv_bfloat16 g_vtl[BB*HH*DH*SS]; // V^T split-lo

__device__ __forceinline__ uint32_t smem_u32(const void* p) {
    uint32_t a;
    asm("{ .reg .u64 t; cvta.to.shared.u64 t, %1; cvt.u32.u64 %0, t; }" : "=r"(a) : "l"(p));
    return a;
}
__device__ __forceinline__ void ldmx4(uint32_t* r, uint32_t addr) {
    asm volatile("ldmatrix.sync.aligned.m8n8.x4.shared.b16 {%0,%1,%2,%3}, [%4];"
        : "=r"(r[0]), "=r"(r[1]), "=r"(r[2]), "=r"(r[3]) : "r"(addr));
}
__device__ __forceinline__ void mma16816(float* c, const uint32_t* a, uint32_t b0, uint32_t b1) {
    asm volatile(
        "mma.sync.aligned.m16n8k16.row.col.f32.bf16.bf16.f32 "
        "{%0,%1,%2,%3},{%4,%5,%6,%7},{%8,%9},{%0,%1,%2,%3};"
        : "+f"(c[0]), "+f"(c[1]), "+f"(c[2]), "+f"(c[3])
        : "r"(a[0]), "r"(a[1]), "r"(a[2]), "r"(a[3]), "r"(b0), "r"(b1));
}
__device__ __forceinline__ uint32_t pack_bf2(__nv_bfloat16 a, __nv_bfloat16 b) {
    return (uint32_t)__bfloat16_as_ushort(a) | ((uint32_t)__bfloat16_as_ushort(b) << 16);
}
__device__ __forceinline__ uint32_t swz(uint32_t off) {
    return off ^ ((off >> 3) & 0x70);
}

// ---------------------------------------------------------------------------
// K0: split hid and W into bf16 hi/lo pairs.
// ---------------------------------------------------------------------------
__global__ __launch_bounds__(256) void split_kernel(
    const float* __restrict__ hid,
    const float* __restrict__ Wq, const float* __restrict__ Wk,
    const float* __restrict__ Wv)
{
    int i = blockIdx.x * 256 + threadIdx.x;
    if (i < BB*SS*DD) {
        float x = hid[i];
        __nv_bfloat16 h = __float2bfloat16(x);
        g_hh[i] = h;
        g_hl[i] = __float2bfloat16(x - __bfloat162float(h));
    }
    if (i < DD*DD) {
        float x = Wq[i];
        __nv_bfloat16 h = __float2bfloat16(x);
        g_wh[i] = h;
        g_wl[i] = __float2bfloat16(x - __bfloat162float(h));

        x = Wk[i];
        h = __float2bfloat16(x);
        g_wh[DD*DD + i] = h;
        g_wl[DD*DD + i] = __float2bfloat16(x - __bfloat162float(h));

        x = Wv[i];
        h = __float2bfloat16(x);
        g_wh[2*DD*DD + i] = h;
        g_wl[2*DD*DD + i] = __float2bfloat16(x - __bfloat162float(h));
    }
}

// ---------------------------------------------------------------------------
// K1 (mma.sync HMMA 3-split): QKV projection.
// NT GEMM M=4096 (b*s), N=768 (h*d), K=768, tiles 128x128, k-chunks of 64.
// Epilogue: +bias, then split-write to g_q*/g_k* (q pre-scaled 1/8) or V^T.
// ---------------------------------------------------------------------------
#define QKV_SMEM (4*16384)   // AH | AL | BH | BL, each 128 rows x 128B

__global__ __launch_bounds__(256) void qkv_mma_kernel(
    const float* __restrict__ bq, const float* __restrict__ bk,
    const float* __restrict__ bv)
{
    extern __shared__ __align__(1024) char smem[];
    const int OF_AH = 0, OF_AL = 16384, OF_BH = 32768, OF_BL = 49152;

    const int tid = threadIdx.x;
    const int z = blockIdx.z;
    const int m0 = blockIdx.y * 128;
    const int n0 = blockIdx.x * 128;
    const uint32_t sb = smem_u32(smem);

    const __nv_bfloat16* Wh = g_wh + (size_t)z * DD * DD;
    const __nv_bfloat16* Wl = g_wl + (size_t)z * DD * DD;
    const float* bias = (z == 0) ? bq : (z == 1) ? bk : bv;

    const int wid = tid >> 5, lane = tid & 31;
    const int wm = wid & 3, wn = wid >> 2;
    const int mw0 = wm * 32;
    const int nw0 = wn * 64;
    const int lrow = lane & 15;
    const int lkh  = (lane >> 4) * 16;

    float acc[2][8][4];
#pragma unroll
    for (int i = 0; i < 2; i++)
#pragma unroll
        for (int j = 0; j < 8; j++)
#pragma unroll
            for (int q = 0; q < 4; q++) acc[i][j][q] = 0.f;

    for (int kc = 0; kc < DD; kc += 64) {
        // stage A (hid rows m0..m0+128, cols kc..kc+64) and B (W rows n0..)
        for (int i = tid; i < 1024; i += 256) {
            int row = i >> 3, u = i & 7;
            uint32_t sw = swz((uint32_t)(row*128 + u*16));
            size_t ga = (size_t)(m0 + row)*DD + kc + u*8;
            *(uint4*)(smem + OF_AH + sw) = *(const uint4*)(g_hh + ga);
            *(uint4*)(smem + OF_AL + sw) = *(const uint4*)(g_hl + ga);
            size_t gb = (size_t)(n0 + row)*DD + kc + u*8;
            *(uint4*)(smem + OF_BH + sw) = *(const uint4*)(Wh + gb);
            *(uint4*)(smem + OF_BL + sw) = *(const uint4*)(Wl + gb);
        }
        __syncthreads();

#pragma unroll
        for (int ks = 0; ks < 4; ks++) {
            const uint32_t colb = (uint32_t)(ks*32 + lkh);
            uint32_t afh[2][4], afl[2][4];
#pragma unroll
            for (int mi = 0; mi < 2; mi++) {
                uint32_t sw = swz((uint32_t)(mw0 + mi*16 + lrow) * 128 + colb);
                ldmx4(afh[mi], sb + OF_AH + sw);
                ldmx4(afl[mi], sb + OF_AL + sw);
            }
            uint32_t bfh[4][4], bfl[4][4];
#pragma unroll
            for (int nj = 0; nj < 4; nj++) {
                uint32_t sw = swz((uint32_t)(nw0 + nj*16 + lrow) * 128 + colb);
                ldmx4(bfh[nj], sb + OF_BH + sw);
                ldmx4(bfl[nj], sb + OF_BL + sw);
            }
#pragma unroll
            for (int mi = 0; mi < 2; mi++)
#pragma unroll
                for (int nj = 0; nj < 4; nj++) {
                    mma16816(acc[mi][nj*2+0], afh[mi], bfh[nj][0], bfh[nj][2]);
                    mma16816(acc[mi][nj*2+1], afh[mi], bfh[nj][1], bfh[nj][3]);
                    mma16816(acc[mi][nj*2+0], afh[mi], bfl[nj][0], bfl[nj][2]);
                    mma16816(acc[mi][nj*2+1], afh[mi], bfl[nj][1], bfl[nj][3]);
                    mma16816(acc[mi][nj*2+0], afl[mi], bfh[nj][0], bfh[nj][2]);
                    mma16816(acc[mi][nj*2+1], afl[mi], bfh[nj][1], bfh[nj][3]);
                }
        }
        __syncthreads();
    }

    // ---- epilogue: +bias, split, write ----
    const float sc = (z == 0) ? 0.125f : 1.0f;
    __nv_bfloat16* oh = (z == 0) ? g_qh : g_kh;
    __nv_bfloat16* ol = (z == 0) ? g_ql : g_kl;

#pragma unroll
    for (int mi = 0; mi < 2; mi++) {
#pragma unroll
        for (int half = 0; half < 2; half++) {
            int m = m0 + mw0 + mi*16 + (lane >> 2) + half*8;
            int b = m >> 11, s = m & 2047;
#pragma unroll
            for (int nj = 0; nj < 8; nj++) {
                int n = n0 + nw0 + nj*8 + (lane & 3)*2;
                float x0 = acc[mi][nj][half*2+0] + bias[n];
                float x1 = acc[mi][nj][half*2+1] + bias[n+1];
                if (z == 2) {
                    // V^T: idx = ((bh)*DH + d)*SS + s
                    int h = n >> 6, d = n & 63;
                    __nv_bfloat16 h0 = __float2bfloat16(x0);
                    __nv_bfloat16 h1 = __float2bfloat16(x1);
                    size_t i0 = ((size_t)((b*HH + h)*DH + d))*SS + s;
                    size_t i1 = ((size_t)((b*HH + h)*DH + d + 1))*SS + s;
                    g_vth[i0] = h0;
                    g_vtl[i0] = __float2bfloat16(x0 - __bfloat162float(h0));
                    g_vth[i1] = h1;
                    g_vtl[i1] = __float2bfloat16(x1 - __bfloat162float(h1));
                } else {
                    x0 *= sc; x1 *= sc;
                    int h = n >> 6, d = n & 63;
                    __nv_bfloat16 h0 = __float2bfloat16(x0);
                    __nv_bfloat16 h1 = __float2bfloat16(x1);
                    size_t idx = (((size_t)(b*HH + h)*SS + s) << 6) + d;
                    *(uint32_t*)(oh + idx) = pack_bf2(h0, h1);
                    *(uint32_t*)(ol + idx) = pack_bf2(
                        __float2bfloat16(x0 - __bfloat162float(h0)),
                        __float2bfloat16(x1 - __bfloat162float(h1)));
                }
            }
        }
    }
}

// ---------------------------------------------------------------------------
// K2 (fused flash attention, mma.sync HMMA bf16 3-split):
//   S = Qs K^T;  scores_out = S + res;  online softmax over (S+res+mask);
//   ctx = (softmax) @ V.  One pass over K; scores written once, never re-read.
// Per CTA: 64 m-rows (4 warps x 16 rows), chunks of 128 n-cols.
// ---------------------------------------------------------------------------
#define FA_OF_QS 0
#define FA_OF_KH 16384
#define FA_OF_KL 32768
#define FA_OF_VH 49152
#define FA_OF_VL 65536
#define FA_OF_MK 81920
#define FA_SMEM  (81920 + 512)

__global__ __launch_bounds__(128, 2) void fused_attn_kernel(
    const float* __restrict__ res, const float* __restrict__ mask,
    float* __restrict__ out_scores, float* __restrict__ ctx)
{
    extern __shared__ __align__(1024) char smem[];
    const int tid = threadIdx.x;
    const int bh = blockIdx.y;
    const int b = bh / HH, h = bh % HH;
    const int m0 = blockIdx.x * 64;
    const uint32_t sb = smem_u32(smem);

    const int wid = tid >> 5, lane = tid & 31;
    const int lrow = lane & 15;
    const int lkh  = (lane >> 4) * 16;
    const int cbase = (lane & 3) * 2;
    const int wrow = wid * 16;              // warp's row base within 64-tile

    float* masksm = (float*)(smem + FA_OF_MK);

    // --- Stage Q hi/lo (64 rows x 64 k) and load resident A-frags ---
    {
        const uint4* sqh = (const uint4*)(g_qh + (size_t)(bh*SS + m0)*DH);
        const uint4* sql = (const uint4*)(g_ql + (size_t)(bh*SS + m0)*DH);
        for (int i = tid; i < 512; i += 128) {
            uint32_t sw = swz((uint32_t)i * 16);
            *(uint4*)(smem + FA_OF_QS + sw) = sqh[i];
            *(uint4*)(smem + FA_OF_QS + 8192 + sw) = sql[i];
        }
    }
    __syncthreads();

    uint32_t qa_h[4][4], qa_l[4][4];
#pragma unroll
    for (int t = 0; t < 4; t++) {
        uint32_t sw = swz((uint32_t)(wrow + lrow) * 128 + t*32 + lkh);
        ldmx4(qa_h[t], sb + FA_OF_QS + sw);
        ldmx4(qa_l[t], sb + FA_OF_QS + 8192 + sw);
    }

    // --- running stats + O accumulator ---
    float mrun0 = -CUDART_INF_F, mrun1 = -CUDART_INF_F;
    float lrun0 = 0.f, lrun1 = 0.f;
    float O[8][4];
#pragma unroll
    for (int j = 0; j < 8; j++)
#pragma unroll
        for (int q = 0; q < 4; q++) O[j][q] = 0.f;

    const int r0 = wrow + (lane >> 2);      // thread's row A (0..63)
    const int r1 = r0 + 8;                  // row B
    const float* Rrow0 = res + (size_t)bh*SS*SS + (size_t)(m0 + r0)*SS;
    const float* Rrow1 = res + (size_t)bh*SS*SS + (size_t)(m0 + r1)*SS;
    float* Srow0 = out_scores + (size_t)bh*SS*SS + (size_t)(m0 + r0)*SS;
    float* Srow1 = out_scores + (size_t)bh*SS*SS + (size_t)(m0 + r1)*SS;
    const __nv_bfloat16* vth = g_vth + (size_t)(bh*DH)*SS;
    const __nv_bfloat16* vtl = g_vtl + (size_t)(bh*DH)*SS;
    const __nv_bfloat16* kph = g_kh + (size_t)(bh*SS)*DH;
    const __nv_bfloat16* kpl = g_kl + (size_t)(bh*SS)*DH;

    for (int n0 = 0; n0 < SS; n0 += 128) {
        // ---- stage K (128 x 64) hi/lo ----
        {
            const uint4* skh = (const uint4*)(kph + (size_t)n0*DH);
            const uint4* skl = (const uint4*)(kpl + (size_t)n0*DH);
            for (int i = tid; i < 1024; i += 128) {
                uint32_t sw = swz((uint32_t)i * 16);
                *(uint4*)(smem + FA_OF_KH + sw) = skh[i];
                *(uint4*)(smem + FA_OF_KL + sw) = skl[i];
            }
        }
        // ---- stage V^T subtiles: [sub][d 0..63][s 64] hi/lo ----
        for (int i = tid; i < 1024; i += 128) {
            int sub = i >> 9, rem = i & 511;
            int d = rem >> 3, u = rem & 7;
            size_t g = (size_t)d * SS + n0 + sub*64 + u*8;
            uint32_t sw = swz((uint32_t)(d*128 + u*16));
            *(uint4*)(smem + FA_OF_VH + sub*8192 + sw) = *(const uint4*)(vth + g);
            *(uint4*)(smem + FA_OF_VL + sub*8192 + sw) = *(const uint4*)(vtl + g);
        }
        masksm[tid] = mask[(size_t)b*SS + n0 + tid];
        __syncthreads();

        // ---- S = Qs K^T (3-split) ----
        float sfr[16][4];
#pragma unroll
        for (int j = 0; j < 16; j++)
#pragma unroll
            for (int q = 0; q < 4; q++) sfr[j][q] = 0.f;

#pragma unroll
        for (int kt = 0; kt < 4; kt++) {
            const uint32_t colb = (uint32_t)(kt*32 + lkh);
#pragma unroll
            for (int j = 0; j < 8; j++) {
                uint32_t sw = swz((uint32_t)(j*16 + lrow) * 128 + colb);
                uint32_t bb[4];
                ldmx4(bb, sb + FA_OF_KH + sw);
                mma16816(sfr[2*j+0], qa_h[kt], bb[0], bb[2]);
                mma16816(sfr[2*j+1], qa_h[kt], bb[1], bb[3]);
                mma16816(sfr[2*j+0], qa_l[kt], bb[0], bb[2]);
                mma16816(sfr[2*j+1], qa_l[kt], bb[1], bb[3]);
                ldmx4(bb, sb + FA_OF_KL + sw);
                mma16816(sfr[2*j+0], qa_h[kt], bb[0], bb[2]);
                mma16816(sfr[2*j+1], qa_h[kt], bb[1], bb[3]);
            }
        }

        // ---- +res, write scores, +mask, tile max ----
        float tmax0 = -CUDART_INF_F, tmax1 = -CUDART_INF_F;
#pragma unroll
        for (int j = 0; j < 16; j++) {
            int col = n0 + j*8 + cbase;
            float2 rv0 = *(const float2*)(Rrow0 + col);
            float2 rv1 = *(const float2*)(Rrow1 + col);
            float s00 = sfr[j][0] + rv0.x, s01 = sfr[j][1] + rv0.y;
            float s10 = sfr[j][2] + rv1.x, s11 = sfr[j][3] + rv1.y;
            *(float2*)(Srow0 + col) = make_float2(s00, s01);
            *(float2*)(Srow1 + col) = make_float2(s10, s11);
            float mk0 = masksm[j*8 + cbase], mk1 = masksm[j*8 + cbase + 1];
            s00 += mk0; s01 += mk1; s10 += mk0; s11 += mk1;
            sfr[j][0] = s00; sfr[j][1] = s01; sfr[j][2] = s10; sfr[j][3] = s11;
            tmax0 = fmaxf(tmax0, fmaxf(s00, s01));
            tmax1 = fmaxf(tmax1, fmaxf(s10, s11));
        }
        tmax0 = fmaxf(tmax0, __shfl_xor_sync(0xffffffffu, tmax0, 1));
        tmax0 = fmaxf(tmax0, __shfl_xor_sync(0xffffffffu, tmax0, 2));
        tmax1 = fmaxf(tmax1, __shfl_xor_sync(0xffffffffu, tmax1, 1));
        tmax1 = fmaxf(tmax1, __shfl_xor_sync(0xffffffffu, tmax1, 2));

        // ---- online rescale ----
        float mnew0 = fmaxf(mrun0, tmax0);
        float mnew1 = fmaxf(mrun1, tmax1);
        float sc0 = __expf(mrun0 - mnew0);
        float sc1 = __expf(mrun1 - mnew1);
        mrun0 = mnew0; mrun1 = mnew1;
        lrun0 *= sc0; lrun1 *= sc1;
#pragma unroll
        for (int j = 0; j < 8; j++) {
            O[j][0] *= sc0; O[j][1] *= sc0;
            O[j][2] *= sc1; O[j][3] *= sc1;
        }

        // ---- exp + pack P into A-frags (hi/lo) ----
        uint32_t pah[8][4], pal[8][4];
#pragma unroll
        for (int j = 0; j < 16; j++) {
            float e0 = __expf(sfr[j][0] - mnew0);
            float e1 = __expf(sfr[j][1] - mnew0);
            float e2 = __expf(sfr[j][2] - mnew1);
            float e3 = __expf(sfr[j][3] - mnew1);
            lrun0 += e0 + e1;
            lrun1 += e2 + e3;
            __nv_bfloat16 h0 = __float2bfloat16(e0), h1 = __float2bfloat16(e1);
            __nv_bfloat16 h2 = __float2bfloat16(e2), h3 = __float2bfloat16(e3);
            int t = j >> 1, odd = j & 1;
            pah[t][odd*2+0] = pack_bf2(h0, h1);
            pah[t][odd*2+1] = pack_bf2(h2, h3);
            pal[t][odd*2+0] = pack_bf2(__float2bfloat16(e0 - __bfloat162float(h0)),
                                       __float2bfloat16(e1 - __bfloat162float(h1)));
            pal[t][odd*2+1] = pack_bf2(__float2bfloat16(e2 - __bfloat162float(h2)),
                                       __float2bfloat16(e3 - __bfloat162float(h3)));
        }

        // ---- O += P V (3-split) ----
#pragma unroll
        for (int t = 0; t < 8; t++) {
            int sub = t >> 2, ks = t & 3;
            const uint32_t colb = (uint32_t)(ks*32 + lkh);
#pragma unroll
            for (int nj = 0; nj < 4; nj++) {
                uint32_t sw = swz((uint32_t)(nj*16 + lrow) * 128 + colb);
                uint32_t vv[4];
                ldmx4(vv, sb + FA_OF_VH + sub*8192 + sw);
                mma16816(O[2*nj+0], pah[t], vv[0], vv[2]);
                mma16816(O[2*nj+1], pah[t], vv[1], vv[3]);
                mma16816(O[2*nj+0], pal[t], vv[0], vv[2]);
                mma16816(O[2*nj+1], pal[t], vv[1], vv[3]);
                ldmx4(vv, sb + FA_OF_VL + sub*8192 + sw);
                mma16816(O[2*nj+0], pah[t], vv[0], vv[2]);
                mma16816(O[2*nj+1], pah[t], vv[1], vv[3]);
            }
        }
        __syncthreads();
    }

    // ---- finalize: reduce l across 4-lane group, scale, write ctx ----
    lrun0 += __shfl_xor_sync(0xffffffffu, lrun0, 1);
    lrun0 += __shfl_xor_sync(0xffffffffu, lrun0, 2);
    lrun1 += __shfl_xor_sync(0xffffffffu, lrun1, 1);
    lrun1 += __shfl_xor_sync(0xffffffffu, lrun1, 2);
    float rl0 = 1.0f / lrun0;
    float rl1 = 1.0f / lrun1;

    float* c0 = ctx + ((size_t)b*SS + m0 + r0)*DD + h*DH + cbase;
    float* c1 = ctx + ((size_t)b*SS + m0 + r1)*DD + h*DH + cbase;
#pragma unroll
    for (int nj = 0; nj < 8; nj++) {
        *(float2*)(c0 + nj*8) = make_float2(O[nj][0]*rl0, O[nj][1]*rl0);
        *(float2*)(c1 + nj*8) = make_float2(O[nj][2]*rl1, O[nj][3]*rl1);
    }
}

// ---------------------------------------------------------------------------
extern "C" void kernel_launch(void* const* d_in, const int* in_sizes, int n_in,
                              void* d_out, int out_size)
{
    const float* hid  = (const float*)d_in[0];
    const float* mask = (const float*)d_in[1];
    const float* res  = (const float*)d_in[2];
    const float* Wq = (const float*)d_in[3];
    const float* bq = (const float*)d_in[4];
    const float* Wk = (const float*)d_in[5];
    const float* bk = (const float*)d_in[6];
    const float* Wv = (const float*)d_in[7];
    const float* bv = (const float*)d_in[8];

    float* out_ctx    = (float*)d_out;
    float* out_scores = (float*)d_out + (size_t)BB*SS*DD;

    cudaFuncSetAttribute(qkv_mma_kernel,
                         cudaFuncAttributeMaxDynamicSharedMemorySize, QKV_SMEM);
    cudaFuncSetAttribute(fused_attn_kernel,
                         cudaFuncAttributeMaxDynamicSharedMemorySize, FA_SMEM);

    split_kernel<<<(BB*SS*DD + 255)/256, 256>>>(hid, Wq, Wk, Wv);
    qkv_mma_kernel<<<dim3(DD/128, (BB*SS)/128, 3), 256, QKV_SMEM>>>(bq, bk, bv);
    fused_attn_kernel<<<dim3(SS/64, BH), 128, FA_SMEM>>>(res, mask, out_scores, out_ctx);
}

// round 13
// speedup vs baseline: 2.0644x; 1.1447x over previous
#include <cuda_runtime.h>
#include <cuda_bf16.h>
#include <math_constants.h>
#include <cstdint>

// Problem dims (fixed)
#define BB 2
#define SS 2048
#define DD 768
#define HH 12
#define DH 64
#define BH (BB*HH)          // 24
#define ROWS_TOTAL (BB*HH*SS) // 49152

typedef unsigned long long u64;

// Scratch (device globals: sanctioned scratch mechanism)
__device__ __nv_bfloat16 g_hh[BB*SS*DD];     // hidden split-hi
__device__ __nv_bfloat16 g_hl[BB*SS*DD];     // hidden split-lo
__device__ __nv_bfloat16 g_wh[3*DD*DD];      // Wq|Wk|Wv split-hi
__device__ __nv_bfloat16 g_wl[3*DD*DD];      // Wq|Wk|Wv split-lo
__device__ __nv_bfloat16 g_qh[BB*HH*SS*DH];  // Q*0.125 split-hi
__device__ __nv_bfloat16 g_ql[BB*HH*SS*DH];  // Q*0.125 split-lo
__device__ __nv_bfloat16 g_kh[BB*HH*SS*DH];
__device__ __nv_bfloat16 g_kl[BB*HH*SS*DH];
__device__ __nv_bfloat16 g_vth[BB*HH*DH*SS]; // V^T [bh][d][s] split-hi
__device__ __nv_bfloat16 g_vtl[BB*HH*DH*SS]; // V^T split-lo

__device__ __forceinline__ uint32_t smem_u32(const void* p) {
    uint32_t a;
    asm("{ .reg .u64 t; cvta.to.shared.u64 t, %1; cvt.u32.u64 %0, t; }" : "=r"(a) : "l"(p));
    return a;
}
__device__ __forceinline__ void ldmx4(uint32_t* r, uint32_t addr) {
    asm volatile("ldmatrix.sync.aligned.m8n8.x4.shared.b16 {%0,%1,%2,%3}, [%4];"
        : "=r"(r[0]), "=r"(r[1]), "=r"(r[2]), "=r"(r[3]) : "r"(addr));
}
__device__ __forceinline__ void mma16816(float* c, const uint32_t* a, uint32_t b0, uint32_t b1) {
    asm volatile(
        "mma.sync.aligned.m16n8k16.row.col.f32.bf16.bf16.f32 "
        "{%0,%1,%2,%3},{%4,%5,%6,%7},{%8,%9},{%0,%1,%2,%3};"
        : "+f"(c[0]), "+f"(c[1]), "+f"(c[2]), "+f"(c[3])
        : "r"(a[0]), "r"(a[1]), "r"(a[2]), "r"(a[3]), "r"(b0), "r"(b1));
}
__device__ __forceinline__ uint32_t pack_bf2(__nv_bfloat16 a, __nv_bfloat16 b) {
    return (uint32_t)__bfloat16_as_ushort(a) | ((uint32_t)__bfloat16_as_ushort(b) << 16);
}
__device__ __forceinline__ uint32_t swz(uint32_t off) {
    return off ^ ((off >> 3) & 0x70);
}
__device__ __forceinline__ void cp16(uint32_t smem_addr, const void* gptr) {
    asm volatile("cp.async.cg.shared.global [%0], [%1], 16;"
                 :: "r"(smem_addr), "l"(gptr) : "memory");
}
#define CP_COMMIT() asm volatile("cp.async.commit_group;" ::: "memory")

// ---------------------------------------------------------------------------
// K0: split hid and W into bf16 hi/lo pairs.
// ---------------------------------------------------------------------------
__global__ __launch_bounds__(256) void split_kernel(
    const float* __restrict__ hid,
    const float* __restrict__ Wq, const float* __restrict__ Wk,
    const float* __restrict__ Wv)
{
    int i = blockIdx.x * 256 + threadIdx.x;
    if (i < BB*SS*DD) {
        float x = hid[i];
        __nv_bfloat16 h = __float2bfloat16(x);
        g_hh[i] = h;
        g_hl[i] = __float2bfloat16(x - __bfloat162float(h));
    }
    if (i < DD*DD) {
        float x = Wq[i];
        __nv_bfloat16 h = __float2bfloat16(x);
        g_wh[i] = h;
        g_wl[i] = __float2bfloat16(x - __bfloat162float(h));

        x = Wk[i];
        h = __float2bfloat16(x);
        g_wh[DD*DD + i] = h;
        g_wl[DD*DD + i] = __float2bfloat16(x - __bfloat162float(h));

        x = Wv[i];
        h = __float2bfloat16(x);
        g_wh[2*DD*DD + i] = h;
        g_wl[2*DD*DD + i] = __float2bfloat16(x - __bfloat162float(h));
    }
}

// ---------------------------------------------------------------------------
// K1 (mma.sync HMMA 3-split): QKV projection.
// ---------------------------------------------------------------------------
#define QKV_SMEM (4*16384)   // AH | AL | BH | BL, each 128 rows x 128B

__global__ __launch_bounds__(256) void qkv_mma_kernel(
    const float* __restrict__ bq, const float* __restrict__ bk,
    const float* __restrict__ bv)
{
    extern __shared__ __align__(1024) char smem[];
    const int OF_AH = 0, OF_AL = 16384, OF_BH = 32768, OF_BL = 49152;

    const int tid = threadIdx.x;
    const int z = blockIdx.z;
    const int m0 = blockIdx.y * 128;
    const int n0 = blockIdx.x * 128;
    const uint32_t sb = smem_u32(smem);

    const __nv_bfloat16* Wh = g_wh + (size_t)z * DD * DD;
    const __nv_bfloat16* Wl = g_wl + (size_t)z * DD * DD;
    const float* bias = (z == 0) ? bq : (z == 1) ? bk : bv;

    const int wid = tid >> 5, lane = tid & 31;
    const int wm = wid & 3, wn = wid >> 2;
    const int mw0 = wm * 32;
    const int nw0 = wn * 64;
    const int lrow = lane & 15;
    const int lkh  = (lane >> 4) * 16;

    float acc[2][8][4];
#pragma unroll
    for (int i = 0; i < 2; i++)
#pragma unroll
        for (int j = 0; j < 8; j++)
#pragma unroll
            for (int q = 0; q < 4; q++) acc[i][j][q] = 0.f;

    for (int kc = 0; kc < DD; kc += 64) {
        for (int i = tid; i < 1024; i += 256) {
            int row = i >> 3, u = i & 7;
            uint32_t sw = swz((uint32_t)(row*128 + u*16));
            size_t ga = (size_t)(m0 + row)*DD + kc + u*8;
            *(uint4*)(smem + OF_AH + sw) = *(const uint4*)(g_hh + ga);
            *(uint4*)(smem + OF_AL + sw) = *(const uint4*)(g_hl + ga);
            size_t gb = (size_t)(n0 + row)*DD + kc + u*8;
            *(uint4*)(smem + OF_BH + sw) = *(const uint4*)(Wh + gb);
            *(uint4*)(smem + OF_BL + sw) = *(const uint4*)(Wl + gb);
        }
        __syncthreads();

#pragma unroll
        for (int ks = 0; ks < 4; ks++) {
            const uint32_t colb = (uint32_t)(ks*32 + lkh);
            uint32_t afh[2][4], afl[2][4];
#pragma unroll
            for (int mi = 0; mi < 2; mi++) {
                uint32_t sw = swz((uint32_t)(mw0 + mi*16 + lrow) * 128 + colb);
                ldmx4(afh[mi], sb + OF_AH + sw);
                ldmx4(afl[mi], sb + OF_AL + sw);
            }
            uint32_t bfh[4][4], bfl[4][4];
#pragma unroll
            for (int nj = 0; nj < 4; nj++) {
                uint32_t sw = swz((uint32_t)(nw0 + nj*16 + lrow) * 128 + colb);
                ldmx4(bfh[nj], sb + OF_BH + sw);
                ldmx4(bfl[nj], sb + OF_BL + sw);
            }
#pragma unroll
            for (int mi = 0; mi < 2; mi++)
#pragma unroll
                for (int nj = 0; nj < 4; nj++) {
                    mma16816(acc[mi][nj*2+0], afh[mi], bfh[nj][0], bfh[nj][2]);
                    mma16816(acc[mi][nj*2+1], afh[mi], bfh[nj][1], bfh[nj][3]);
                    mma16816(acc[mi][nj*2+0], afh[mi], bfl[nj][0], bfl[nj][2]);
                    mma16816(acc[mi][nj*2+1], afh[mi], bfl[nj][1], bfl[nj][3]);
                    mma16816(acc[mi][nj*2+0], afl[mi], bfh[nj][0], bfh[nj][2]);
                    mma16816(acc[mi][nj*2+1], afl[mi], bfh[nj][1], bfh[nj][3]);
                }
        }
        __syncthreads();
    }

    const float sc = (z == 0) ? 0.125f : 1.0f;
    __nv_bfloat16* oh = (z == 0) ? g_qh : g_kh;
    __nv_bfloat16* ol = (z == 0) ? g_ql : g_kl;

#pragma unroll
    for (int mi = 0; mi < 2; mi++) {
#pragma unroll
        for (int half = 0; half < 2; half++) {
            int m = m0 + mw0 + mi*16 + (lane >> 2) + half*8;
            int b = m >> 11, s = m & 2047;
#pragma unroll
            for (int nj = 0; nj < 8; nj++) {
                int n = n0 + nw0 + nj*8 + (lane & 3)*2;
                float x0 = acc[mi][nj][half*2+0] + bias[n];
                float x1 = acc[mi][nj][half*2+1] + bias[n+1];
                if (z == 2) {
                    int h = n >> 6, d = n & 63;
                    __nv_bfloat16 h0 = __float2bfloat16(x0);
                    __nv_bfloat16 h1 = __float2bfloat16(x1);
                    size_t i0 = ((size_t)((b*HH + h)*DH + d))*SS + s;
                    size_t i1 = ((size_t)((b*HH + h)*DH + d + 1))*SS + s;
                    g_vth[i0] = h0;
                    g_vtl[i0] = __float2bfloat16(x0 - __bfloat162float(h0));
                    g_vth[i1] = h1;
                    g_vtl[i1] = __float2bfloat16(x1 - __bfloat162float(h1));
                } else {
                    x0 *= sc; x1 *= sc;
                    int h = n >> 6, d = n & 63;
                    __nv_bfloat16 h0 = __float2bfloat16(x0);
                    __nv_bfloat16 h1 = __float2bfloat16(x1);
                    size_t idx = (((size_t)(b*HH + h)*SS + s) << 6) + d;
                    *(uint32_t*)(oh + idx) = pack_bf2(h0, h1);
                    *(uint32_t*)(ol + idx) = pack_bf2(
                        __float2bfloat16(x0 - __bfloat162float(h0)),
                        __float2bfloat16(x1 - __bfloat162float(h1)));
                }
            }
        }
    }
}

// ---------------------------------------------------------------------------
// K2 (fused flash attention, cp.async pipelined):
// K/mask double-buffered; V issued per-iter and awaited with wait_group 1.
// smem: Kbuf0 32K | Kbuf1 32K (Q staged here first) | VH+VL 32K | mask 2x512
// ---------------------------------------------------------------------------
#define FA_OF_V  65536
#define FA_OF_MK 98304
#define FA_SMEM  (98304 + 1024)

__global__ __launch_bounds__(128, 2) void fused_attn_kernel(
    const float* __restrict__ res, const float* __restrict__ mask,
    float* __restrict__ out_scores, float* __restrict__ ctx)
{
    extern __shared__ __align__(1024) char smem[];
    const int tid = threadIdx.x;
    const int bh = blockIdx.y;
    const int b = bh / HH, h = bh % HH;
    const int m0 = blockIdx.x * 64;
    const uint32_t sb = smem_u32(smem);

    const int wid = tid >> 5, lane = tid & 31;
    const int lrow = lane & 15;
    const int lkh  = (lane >> 4) * 16;
    const int cbase = (lane & 3) * 2;
    const int wrow = wid * 16;

    // --- Stage Q hi/lo (64x64) into Kbuf1 region; load resident A-frags ---
    {
        const uint4* sqh = (const uint4*)(g_qh + (size_t)(bh*SS + m0)*DH);
        const uint4* sql = (const uint4*)(g_ql + (size_t)(bh*SS + m0)*DH);
        for (int i = tid; i < 512; i += 128) {
            uint32_t sw = swz((uint32_t)i * 16);
            *(uint4*)(smem + 32768 + sw) = sqh[i];
            *(uint4*)(smem + 32768 + 8192 + sw) = sql[i];
        }
    }
    __syncthreads();

    uint32_t qa_h[4][4], qa_l[4][4];
#pragma unroll
    for (int t = 0; t < 4; t++) {
        uint32_t sw = swz((uint32_t)(wrow + lrow) * 128 + t*32 + lkh);
        ldmx4(qa_h[t], sb + 32768 + sw);
        ldmx4(qa_l[t], sb + 32768 + 8192 + sw);
    }
    __syncthreads();   // Q frags in regs; Kbuf1 free for prefetch reuse

    const __nv_bfloat16* vth = g_vth + (size_t)(bh*DH)*SS;
    const __nv_bfloat16* vtl = g_vtl + (size_t)(bh*DH)*SS;
    const __nv_bfloat16* kph = g_kh + (size_t)(bh*SS)*DH;
    const __nv_bfloat16* kpl = g_kl + (size_t)(bh*SS)*DH;
    const float* mask_g = mask + (size_t)b*SS;

    // --- prefetch chunk 0: K + mask -> buf0 ---
    {
        const uint4* skh = (const uint4*)kph;
        const uint4* skl = (const uint4*)kpl;
        for (int i = tid; i < 1024; i += 128) {
            uint32_t sw = swz((uint32_t)i * 16);
            cp16(sb + sw, skh + i);
            cp16(sb + 16384 + sw, skl + i);
        }
        if (tid < 32) cp16(sb + FA_OF_MK + tid*16, mask_g + tid*4);
    }
    CP_COMMIT();

    // --- running stats + O accumulator ---
    float mrun0 = -CUDART_INF_F, mrun1 = -CUDART_INF_F;
    float lrun0 = 0.f, lrun1 = 0.f;
    float O[8][4];
#pragma unroll
    for (int j = 0; j < 8; j++)
#pragma unroll
        for (int q = 0; q < 4; q++) O[j][q] = 0.f;

    const int r0 = wrow + (lane >> 2);
    const int r1 = r0 + 8;
    const float* Rrow0 = res + (size_t)bh*SS*SS + (size_t)(m0 + r0)*SS;
    const float* Rrow1 = res + (size_t)bh*SS*SS + (size_t)(m0 + r1)*SS;
    float* Srow0 = out_scores + (size_t)bh*SS*SS + (size_t)(m0 + r0)*SS;
    float* Srow1 = out_scores + (size_t)bh*SS*SS + (size_t)(m0 + r1)*SS;

    for (int it = 0; it < 16; it++) {
        const int cur = it & 1;
        const int n0 = it * 128;

        // ---- issue V(it) ----
        for (int i = tid; i < 1024; i += 128) {
            int sub = i >> 9, rem = i & 511;
            int d = rem >> 3, u = rem & 7;
            size_t g = (size_t)d * SS + n0 + sub*64 + u*8;
            uint32_t sw = swz((uint32_t)(d*128 + u*16));
            cp16(sb + FA_OF_V + sub*8192 + sw, vth + g);
            cp16(sb + FA_OF_V + 16384 + sub*8192 + sw, vtl + g);
        }
        CP_COMMIT();

        // ---- issue K(it+1) + mask(it+1) into other buffer ----
        if (it + 1 < 16) {
            const int nn = n0 + 128;
            const uint4* skh = (const uint4*)(kph + (size_t)nn*DH);
            const uint4* skl = (const uint4*)(kpl + (size_t)nn*DH);
            const uint32_t kb = (uint32_t)(1 - cur) * 32768;
            for (int i = tid; i < 1024; i += 128) {
                uint32_t sw = swz((uint32_t)i * 16);
                cp16(sb + kb + sw, skh + i);
                cp16(sb + kb + 16384 + sw, skl + i);
            }
            if (tid < 32) cp16(sb + FA_OF_MK + (1-cur)*512 + tid*16, mask_g + nn + tid*4);
            CP_COMMIT();
            asm volatile("cp.async.wait_group 1;" ::: "memory");
        } else {
            asm volatile("cp.async.wait_group 0;" ::: "memory");
        }
        __syncthreads();

        const uint32_t kb = (uint32_t)cur * 32768;
        const float* masksm = (const float*)(smem + FA_OF_MK + cur*512);

        // ---- S = Qs K^T (3-split) ----
        float sfr[16][4];
#pragma unroll
        for (int j = 0; j < 16; j++)
#pragma unroll
            for (int q = 0; q < 4; q++) sfr[j][q] = 0.f;

#pragma unroll
        for (int kt = 0; kt < 4; kt++) {
            const uint32_t colb = (uint32_t)(kt*32 + lkh);
#pragma unroll
            for (int j = 0; j < 8; j++) {
                uint32_t sw = swz((uint32_t)(j*16 + lrow) * 128 + colb);
                uint32_t bb[4];
                ldmx4(bb, sb + kb + sw);
                mma16816(sfr[2*j+0], qa_h[kt], bb[0], bb[2]);
                mma16816(sfr[2*j+1], qa_h[kt], bb[1], bb[3]);
                mma16816(sfr[2*j+0], qa_l[kt], bb[0], bb[2]);
                mma16816(sfr[2*j+1], qa_l[kt], bb[1], bb[3]);
                ldmx4(bb, sb + kb + 16384 + sw);
                mma16816(sfr[2*j+0], qa_h[kt], bb[0], bb[2]);
                mma16816(sfr[2*j+1], qa_h[kt], bb[1], bb[3]);
            }
        }

        // ---- +res, write scores, +mask, tile max ----
        float tmax0 = -CUDART_INF_F, tmax1 = -CUDART_INF_F;
#pragma unroll
        for (int j = 0; j < 16; j++) {
            int col = n0 + j*8 + cbase;
            float2 rv0 = *(const float2*)(Rrow0 + col);
            float2 rv1 = *(const float2*)(Rrow1 + col);
            float s00 = sfr[j][0] + rv0.x, s01 = sfr[j][1] + rv0.y;
            float s10 = sfr[j][2] + rv1.x, s11 = sfr[j][3] + rv1.y;
            *(float2*)(Srow0 + col) = make_float2(s00, s01);
            *(float2*)(Srow1 + col) = make_float2(s10, s11);
            float mk0 = masksm[j*8 + cbase], mk1 = masksm[j*8 + cbase + 1];
            s00 += mk0; s01 += mk1; s10 += mk0; s11 += mk1;
            sfr[j][0] = s00; sfr[j][1] = s01; sfr[j][2] = s10; sfr[j][3] = s11;
            tmax0 = fmaxf(tmax0, fmaxf(s00, s01));
            tmax1 = fmaxf(tmax1, fmaxf(s10, s11));
        }
        tmax0 = fmaxf(tmax0, __shfl_xor_sync(0xffffffffu, tmax0, 1));
        tmax0 = fmaxf(tmax0, __shfl_xor_sync(0xffffffffu, tmax0, 2));
        tmax1 = fmaxf(tmax1, __shfl_xor_sync(0xffffffffu, tmax1, 1));
        tmax1 = fmaxf(tmax1, __shfl_xor_sync(0xffffffffu, tmax1, 2));

        // ---- online rescale ----
        float mnew0 = fmaxf(mrun0, tmax0);
        float mnew1 = fmaxf(mrun1, tmax1);
        float sc0 = __expf(mrun0 - mnew0);
        float sc1 = __expf(mrun1 - mnew1);
        mrun0 = mnew0; mrun1 = mnew1;
        lrun0 *= sc0; lrun1 *= sc1;
#pragma unroll
        for (int j = 0; j < 8; j++) {
            O[j][0] *= sc0; O[j][1] *= sc0;
            O[j][2] *= sc1; O[j][3] *= sc1;
        }

        // ---- exp + pack P into A-frags (hi/lo) ----
        uint32_t pah[8][4], pal[8][4];
#pragma unroll
        for (int j = 0; j < 16; j++) {
            float e0 = __expf(sfr[j][0] - mnew0);
            float e1 = __expf(sfr[j][1] - mnew0);
            float e2 = __expf(sfr[j][2] - mnew1);
            float e3 = __expf(sfr[j][3] - mnew1);
            lrun0 += e0 + e1;
            lrun1 += e2 + e3;
            __nv_bfloat16 h0 = __float2bfloat16(e0), h1 = __float2bfloat16(e1);
            __nv_bfloat16 h2 = __float2bfloat16(e2), h3 = __float2bfloat16(e3);
            int t = j >> 1, odd = j & 1;
            pah[t][odd*2+0] = pack_bf2(h0, h1);
            pah[t][odd*2+1] = pack_bf2(h2, h3);
            pal[t][odd*2+0] = pack_bf2(__float2bfloat16(e0 - __bfloat162float(h0)),
                                       __float2bfloat16(e1 - __bfloat162float(h1)));
            pal[t][odd*2+1] = pack_bf2(__float2bfloat16(e2 - __bfloat162float(h2)),
                                       __float2bfloat16(e3 - __bfloat162float(h3)));
        }

        // ---- O += P V (3-split) ----
#pragma unroll
        for (int t = 0; t < 8; t++) {
            int sub = t >> 2, ks = t & 3;
            const uint32_t colb = (uint32_t)(ks*32 + lkh);
#pragma unroll
            for (int nj = 0; nj < 4; nj++) {
                uint32_t sw = swz((uint32_t)(nj*16 + lrow) * 128 + colb);
                uint32_t vv[4];
                ldmx4(vv, sb + FA_OF_V + sub*8192 + sw);
                mma16816(O[2*nj+0], pah[t], vv[0], vv[2]);
                mma16816(O[2*nj+1], pah[t], vv[1], vv[3]);
                mma16816(O[2*nj+0], pal[t], vv[0], vv[2]);
                mma16816(O[2*nj+1], pal[t], vv[1], vv[3]);
                ldmx4(vv, sb + FA_OF_V + 16384 + sub*8192 + sw);
                mma16816(O[2*nj+0], pah[t], vv[0], vv[2]);
                mma16816(O[2*nj+1], pah[t], vv[1], vv[3]);
            }
        }
        __syncthreads();
    }

    // ---- finalize ----
    lrun0 += __shfl_xor_sync(0xffffffffu, lrun0, 1);
    lrun0 += __shfl_xor_sync(0xffffffffu, lrun0, 2);
    lrun1 += __shfl_xor_sync(0xffffffffu, lrun1, 1);
    lrun1 += __shfl_xor_sync(0xffffffffu, lrun1, 2);
    float rl0 = 1.0f / lrun0;
    float rl1 = 1.0f / lrun1;

    float* c0 = ctx + ((size_t)b*SS + m0 + r0)*DD + h*DH + cbase;
    float* c1 = ctx + ((size_t)b*SS + m0 + r1)*DD + h*DH + cbase;
#pragma unroll
    for (int nj = 0; nj < 8; nj++) {
        *(float2*)(c0 + nj*8) = make_float2(O[nj][0]*rl0, O[nj][1]*rl0);
        *(float2*)(c1 + nj*8) = make_float2(O[nj][2]*rl1, O[nj][3]*rl1);
    }
}

// ---------------------------------------------------------------------------
extern "C" void kernel_launch(void* const* d_in, const int* in_sizes, int n_in,
                              void* d_out, int out_size)
{
    const float* hid  = (const float*)d_in[0];
    const float* mask = (const float*)d_in[1];
    const float* res  = (const float*)d_in[2];
    const float* Wq = (const float*)d_in[3];
    const float* bq = (const float*)d_in[4];
    const float* Wk = (const float*)d_in[5];
    const float* bk = (const float*)d_in[6];
    const float* Wv = (const float*)d_in[7];
    const float* bv = (const float*)d_in[8];

    float* out_ctx    = (float*)d_out;
    float* out_scores = (float*)d_out + (size_t)BB*SS*DD;

    cudaFuncSetAttribute(qkv_mma_kernel,
                         cudaFuncAttributeMaxDynamicSharedMemorySize, QKV_SMEM);
    cudaFuncSetAttribute(fused_attn_kernel,
                         cudaFuncAttributeMaxDynamicSharedMemorySize, FA_SMEM);

    split_kernel<<<(BB*SS*DD + 255)/256, 256>>>(hid, Wq, Wk, Wv);
    qkv_mma_kernel<<<dim3(DD/128, (BB*SS)/128, 3), 256, QKV_SMEM>>>(bq, bk, bv);
    fused_attn_kernel<<<dim3(SS/64, BH), 128, FA_SMEM>>>(res, mask, out_scores, out_ctx);
}

// round 14
// speedup vs baseline: 2.0684x; 1.0019x over previous
#include <cuda_runtime.h>
#include <cuda_bf16.h>
#include <math_constants.h>
#include <cstdint>

// Problem dims (fixed)
#define BB 2
#define SS 2048
#define DD 768
#define HH 12
#define DH 64
#define BH (BB*HH)          // 24
#define ROWS_TOTAL (BB*HH*SS) // 49152

typedef unsigned long long u64;

// Scratch (device globals: sanctioned scratch mechanism)
__device__ __nv_bfloat16 g_hh[BB*SS*DD];     // hidden split-hi
__device__ __nv_bfloat16 g_hl[BB*SS*DD];     // hidden split-lo
__device__ __nv_bfloat16 g_wh[3*DD*DD];      // Wq|Wk|Wv split-hi
__device__ __nv_bfloat16 g_wl[3*DD*DD];      // Wq|Wk|Wv split-lo
__device__ __nv_bfloat16 g_qh[BB*HH*SS*DH];  // Q*0.125 split-hi
__device__ __nv_bfloat16 g_ql[BB*HH*SS*DH];  // Q*0.125 split-lo
__device__ __nv_bfloat16 g_kh[BB*HH*SS*DH];
__device__ __nv_bfloat16 g_kl[BB*HH*SS*DH];
__device__ __nv_bfloat16 g_vth[BB*HH*DH*SS]; // V^T [bh][d][s] split-hi
__device__ __nv_bfloat16 g_vtl[BB*HH*DH*SS]; // V^T split-lo

__device__ __forceinline__ uint32_t smem_u32(const void* p) {
    uint32_t a;
    asm("{ .reg .u64 t; cvta.to.shared.u64 t, %1; cvt.u32.u64 %0, t; }" : "=r"(a) : "l"(p));
    return a;
}
__device__ __forceinline__ void ldmx4(uint32_t* r, uint32_t addr) {
    asm volatile("ldmatrix.sync.aligned.m8n8.x4.shared.b16 {%0,%1,%2,%3}, [%4];"
        : "=r"(r[0]), "=r"(r[1]), "=r"(r[2]), "=r"(r[3]) : "r"(addr));
}
__device__ __forceinline__ void mma16816(float* c, const uint32_t* a, uint32_t b0, uint32_t b1) {
    asm volatile(
        "mma.sync.aligned.m16n8k16.row.col.f32.bf16.bf16.f32 "
        "{%0,%1,%2,%3},{%4,%5,%6,%7},{%8,%9},{%0,%1,%2,%3};"
        : "+f"(c[0]), "+f"(c[1]), "+f"(c[2]), "+f"(c[3])
        : "r"(a[0]), "r"(a[1]), "r"(a[2]), "r"(a[3]), "r"(b0), "r"(b1));
}
__device__ __forceinline__ uint32_t pack_bf2(__nv_bfloat16 a, __nv_bfloat16 b) {
    return (uint32_t)__bfloat16_as_ushort(a) | ((uint32_t)__bfloat16_as_ushort(b) << 16);
}
__device__ __forceinline__ uint32_t swz(uint32_t off) {
    return off ^ ((off >> 3) & 0x70);
}
__device__ __forceinline__ void cp16(uint32_t smem_addr, const void* gptr) {
    asm volatile("cp.async.cg.shared.global [%0], [%1], 16;"
                 :: "r"(smem_addr), "l"(gptr) : "memory");
}
#define CP_COMMIT() asm volatile("cp.async.commit_group;" ::: "memory")

// ---------------------------------------------------------------------------
// K0: split hid and W into bf16 hi/lo pairs.
// ---------------------------------------------------------------------------
__global__ __launch_bounds__(256) void split_kernel(
    const float* __restrict__ hid,
    const float* __restrict__ Wq, const float* __restrict__ Wk,
    const float* __restrict__ Wv)
{
    int i = blockIdx.x * 256 + threadIdx.x;
    if (i < BB*SS*DD) {
        float x = hid[i];
        __nv_bfloat16 h = __float2bfloat16(x);
        g_hh[i] = h;
        g_hl[i] = __float2bfloat16(x - __bfloat162float(h));
    }
    if (i < DD*DD) {
        float x = Wq[i];
        __nv_bfloat16 h = __float2bfloat16(x);
        g_wh[i] = h;
        g_wl[i] = __float2bfloat16(x - __bfloat162float(h));

        x = Wk[i];
        h = __float2bfloat16(x);
        g_wh[DD*DD + i] = h;
        g_wl[DD*DD + i] = __float2bfloat16(x - __bfloat162float(h));

        x = Wv[i];
        h = __float2bfloat16(x);
        g_wh[2*DD*DD + i] = h;
        g_wl[2*DD*DD + i] = __float2bfloat16(x - __bfloat162float(h));
    }
}

// ---------------------------------------------------------------------------
// K1 (mma.sync HMMA 3-split): QKV projection.
// ---------------------------------------------------------------------------
#define QKV_SMEM (4*16384)   // AH | AL | BH | BL, each 128 rows x 128B

__global__ __launch_bounds__(256) void qkv_mma_kernel(
    const float* __restrict__ bq, const float* __restrict__ bk,
    const float* __restrict__ bv)
{
    extern __shared__ __align__(1024) char smem[];
    const int OF_AH = 0, OF_AL = 16384, OF_BH = 32768, OF_BL = 49152;

    const int tid = threadIdx.x;
    const int z = blockIdx.z;
    const int m0 = blockIdx.y * 128;
    const int n0 = blockIdx.x * 128;
    const uint32_t sb = smem_u32(smem);

    const __nv_bfloat16* Wh = g_wh + (size_t)z * DD * DD;
    const __nv_bfloat16* Wl = g_wl + (size_t)z * DD * DD;
    const float* bias = (z == 0) ? bq : (z == 1) ? bk : bv;

    const int wid = tid >> 5, lane = tid & 31;
    const int wm = wid & 3, wn = wid >> 2;
    const int mw0 = wm * 32;
    const int nw0 = wn * 64;
    const int lrow = lane & 15;
    const int lkh  = (lane >> 4) * 16;

    float acc[2][8][4];
#pragma unroll
    for (int i = 0; i < 2; i++)
#pragma unroll
        for (int j = 0; j < 8; j++)
#pragma unroll
            for (int q = 0; q < 4; q++) acc[i][j][q] = 0.f;

    for (int kc = 0; kc < DD; kc += 64) {
        for (int i = tid; i < 1024; i += 256) {
            int row = i >> 3, u = i & 7;
            uint32_t sw = swz((uint32_t)(row*128 + u*16));
            size_t ga = (size_t)(m0 + row)*DD + kc + u*8;
            *(uint4*)(smem + OF_AH + sw) = *(const uint4*)(g_hh + ga);
            *(uint4*)(smem + OF_AL + sw) = *(const uint4*)(g_hl + ga);
            size_t gb = (size_t)(n0 + row)*DD + kc + u*8;
            *(uint4*)(smem + OF_BH + sw) = *(const uint4*)(Wh + gb);
            *(uint4*)(smem + OF_BL + sw) = *(const uint4*)(Wl + gb);
        }
        __syncthreads();

#pragma unroll
        for (int ks = 0; ks < 4; ks++) {
            const uint32_t colb = (uint32_t)(ks*32 + lkh);
            uint32_t afh[2][4], afl[2][4];
#pragma unroll
            for (int mi = 0; mi < 2; mi++) {
                uint32_t sw = swz((uint32_t)(mw0 + mi*16 + lrow) * 128 + colb);
                ldmx4(afh[mi], sb + OF_AH + sw);
                ldmx4(afl[mi], sb + OF_AL + sw);
            }
            uint32_t bfh[4][4], bfl[4][4];
#pragma unroll
            for (int nj = 0; nj < 4; nj++) {
                uint32_t sw = swz((uint32_t)(nw0 + nj*16 + lrow) * 128 + colb);
                ldmx4(bfh[nj], sb + OF_BH + sw);
                ldmx4(bfl[nj], sb + OF_BL + sw);
            }
#pragma unroll
            for (int mi = 0; mi < 2; mi++)
#pragma unroll
                for (int nj = 0; nj < 4; nj++) {
                    mma16816(acc[mi][nj*2+0], afh[mi], bfh[nj][0], bfh[nj][2]);
                    mma16816(acc[mi][nj*2+1], afh[mi], bfh[nj][1], bfh[nj][3]);
                    mma16816(acc[mi][nj*2+0], afh[mi], bfl[nj][0], bfl[nj][2]);
                    mma16816(acc[mi][nj*2+1], afh[mi], bfl[nj][1], bfl[nj][3]);
                    mma16816(acc[mi][nj*2+0], afl[mi], bfh[nj][0], bfh[nj][2]);
                    mma16816(acc[mi][nj*2+1], afl[mi], bfh[nj][1], bfh[nj][3]);
                }
        }
        __syncthreads();
    }

    const float sc = (z == 0) ? 0.125f : 1.0f;
    __nv_bfloat16* oh = (z == 0) ? g_qh : g_kh;
    __nv_bfloat16* ol = (z == 0) ? g_ql : g_kl;

#pragma unroll
    for (int mi = 0; mi < 2; mi++) {
#pragma unroll
        for (int half = 0; half < 2; half++) {
            int m = m0 + mw0 + mi*16 + (lane >> 2) + half*8;
            int b = m >> 11, s = m & 2047;
#pragma unroll
            for (int nj = 0; nj < 8; nj++) {
                int n = n0 + nw0 + nj*8 + (lane & 3)*2;
                float x0 = acc[mi][nj][half*2+0] + bias[n];
                float x1 = acc[mi][nj][half*2+1] + bias[n+1];
                if (z == 2) {
                    int h = n >> 6, d = n & 63;
                    __nv_bfloat16 h0 = __float2bfloat16(x0);
                    __nv_bfloat16 h1 = __float2bfloat16(x1);
                    size_t i0 = ((size_t)((b*HH + h)*DH + d))*SS + s;
                    size_t i1 = ((size_t)((b*HH + h)*DH + d + 1))*SS + s;
                    g_vth[i0] = h0;
                    g_vtl[i0] = __float2bfloat16(x0 - __bfloat162float(h0));
                    g_vth[i1] = h1;
                    g_vtl[i1] = __float2bfloat16(x1 - __bfloat162float(h1));
                } else {
                    x0 *= sc; x1 *= sc;
                    int h = n >> 6, d = n & 63;
                    __nv_bfloat16 h0 = __float2bfloat16(x0);
                    __nv_bfloat16 h1 = __float2bfloat16(x1);
                    size_t idx = (((size_t)(b*HH + h)*SS + s) << 6) + d;
                    *(uint32_t*)(oh + idx) = pack_bf2(h0, h1);
                    *(uint32_t*)(ol + idx) = pack_bf2(
                        __float2bfloat16(x0 - __bfloat162float(h0)),
                        __float2bfloat16(x1 - __bfloat162float(h1)));
                }
            }
        }
    }
}

// ---------------------------------------------------------------------------
// K2 (fused flash attention, cp.async pipelined):
// K/mask double-buffered; V issued per-iter and awaited with wait_group 1.
// smem: Kbuf0 32K | Kbuf1 32K (Q staged here first) | VH+VL 32K | mask 2x512
// ---------------------------------------------------------------------------
#define FA_OF_V  65536
#define FA_OF_MK 98304
#define FA_SMEM  (98304 + 1024)

__global__ __launch_bounds__(128, 2) void fused_attn_kernel(
    const float* __restrict__ res, const float* __restrict__ mask,
    float* __restrict__ out_scores, float* __restrict__ ctx)
{
    extern __shared__ __align__(1024) char smem[];
    const int tid = threadIdx.x;
    const int bh = blockIdx.y;
    const int b = bh / HH, h = bh % HH;
    const int m0 = blockIdx.x * 64;
    const uint32_t sb = smem_u32(smem);

    const int wid = tid >> 5, lane = tid & 31;
    const int lrow = lane & 15;
    const int lkh  = (lane >> 4) * 16;
    const int cbase = (lane & 3) * 2;
    const int wrow = wid * 16;

    // --- Stage Q hi/lo (64x64) into Kbuf1 region; load resident A-frags ---
    {
        const uint4* sqh = (const uint4*)(g_qh + (size_t)(bh*SS + m0)*DH);
        const uint4* sql = (const uint4*)(g_ql + (size_t)(bh*SS + m0)*DH);
        for (int i = tid; i < 512; i += 128) {
            uint32_t sw = swz((uint32_t)i * 16);
            *(uint4*)(smem + 32768 + sw) = sqh[i];
            *(uint4*)(smem + 32768 + 8192 + sw) = sql[i];
        }
    }
    __syncthreads();

    uint32_t qa_h[4][4], qa_l[4][4];
#pragma unroll
    for (int t = 0; t < 4; t++) {
        uint32_t sw = swz((uint32_t)(wrow + lrow) * 128 + t*32 + lkh);
        ldmx4(qa_h[t], sb + 32768 + sw);
        ldmx4(qa_l[t], sb + 32768 + 8192 + sw);
    }
    __syncthreads();   // Q frags in regs; Kbuf1 free for prefetch reuse

    const __nv_bfloat16* vth = g_vth + (size_t)(bh*DH)*SS;
    const __nv_bfloat16* vtl = g_vtl + (size_t)(bh*DH)*SS;
    const __nv_bfloat16* kph = g_kh + (size_t)(bh*SS)*DH;
    const __nv_bfloat16* kpl = g_kl + (size_t)(bh*SS)*DH;
    const float* mask_g = mask + (size_t)b*SS;

    // --- prefetch chunk 0: K + mask -> buf0 ---
    {
        const uint4* skh = (const uint4*)kph;
        const uint4* skl = (const uint4*)kpl;
        for (int i = tid; i < 1024; i += 128) {
            uint32_t sw = swz((uint32_t)i * 16);
            cp16(sb + sw, skh + i);
            cp16(sb + 16384 + sw, skl + i);
        }
        if (tid < 32) cp16(sb + FA_OF_MK + tid*16, mask_g + tid*4);
    }
    CP_COMMIT();

    // --- running stats + O accumulator ---
    float mrun0 = -CUDART_INF_F, mrun1 = -CUDART_INF_F;
    float lrun0 = 0.f, lrun1 = 0.f;
    float O[8][4];
#pragma unroll
    for (int j = 0; j < 8; j++)
#pragma unroll
        for (int q = 0; q < 4; q++) O[j][q] = 0.f;

    const int r0 = wrow + (lane >> 2);
    const int r1 = r0 + 8;
    const float* Rrow0 = res + (size_t)bh*SS*SS + (size_t)(m0 + r0)*SS;
    const float* Rrow1 = res + (size_t)bh*SS*SS + (size_t)(m0 + r1)*SS;
    float* Srow0 = out_scores + (size_t)bh*SS*SS + (size_t)(m0 + r0)*SS;
    float* Srow1 = out_scores + (size_t)bh*SS*SS + (size_t)(m0 + r1)*SS;

    for (int it = 0; it < 16; it++) {
        const int cur = it & 1;
        const int n0 = it * 128;

        // ---- issue V(it) ----
        for (int i = tid; i < 1024; i += 128) {
            int sub = i >> 9, rem = i & 511;
            int d = rem >> 3, u = rem & 7;
            size_t g = (size_t)d * SS + n0 + sub*64 + u*8;
            uint32_t sw = swz((uint32_t)(d*128 + u*16));
            cp16(sb + FA_OF_V + sub*8192 + sw, vth + g);
            cp16(sb + FA_OF_V + 16384 + sub*8192 + sw, vtl + g);
        }
        CP_COMMIT();

        // ---- issue K(it+1) + mask(it+1) into other buffer ----
        if (it + 1 < 16) {
            const int nn = n0 + 128;
            const uint4* skh = (const uint4*)(kph + (size_t)nn*DH);
            const uint4* skl = (const uint4*)(kpl + (size_t)nn*DH);
            const uint32_t kb = (uint32_t)(1 - cur) * 32768;
            for (int i = tid; i < 1024; i += 128) {
                uint32_t sw = swz((uint32_t)i * 16);
                cp16(sb + kb + sw, skh + i);
                cp16(sb + kb + 16384 + sw, skl + i);
            }
            if (tid < 32) cp16(sb + FA_OF_MK + (1-cur)*512 + tid*16, mask_g + nn + tid*4);
            CP_COMMIT();
            asm volatile("cp.async.wait_group 1;" ::: "memory");
        } else {
            asm volatile("cp.async.wait_group 0;" ::: "memory");
        }
        __syncthreads();

        const uint32_t kb = (uint32_t)cur * 32768;
        const float* masksm = (const float*)(smem + FA_OF_MK + cur*512);

        // ---- S = Qs K^T (3-split) ----
        float sfr[16][4];
#pragma unroll
        for (int j = 0; j < 16; j++)
#pragma unroll
            for (int q = 0; q < 4; q++) sfr[j][q] = 0.f;

#pragma unroll
        for (int kt = 0; kt < 4; kt++) {
            const uint32_t colb = (uint32_t)(kt*32 + lkh);
#pragma unroll
            for (int j = 0; j < 8; j++) {
                uint32_t sw = swz((uint32_t)(j*16 + lrow) * 128 + colb);
                uint32_t bb[4];
                ldmx4(bb, sb + kb + sw);
                mma16816(sfr[2*j+0], qa_h[kt], bb[0], bb[2]);
                mma16816(sfr[2*j+1], qa_h[kt], bb[1], bb[3]);
                mma16816(sfr[2*j+0], qa_l[kt], bb[0], bb[2]);
                mma16816(sfr[2*j+1], qa_l[kt], bb[1], bb[3]);
                ldmx4(bb, sb + kb + 16384 + sw);
                mma16816(sfr[2*j+0], qa_h[kt], bb[0], bb[2]);
                mma16816(sfr[2*j+1], qa_h[kt], bb[1], bb[3]);
            }
        }

        // ---- +res, write scores, +mask, tile max ----
        float tmax0 = -CUDART_INF_F, tmax1 = -CUDART_INF_F;
#pragma unroll
        for (int j = 0; j < 16; j++) {
            int col = n0 + j*8 + cbase;
            float2 rv0 = *(const float2*)(Rrow0 + col);
            float2 rv1 = *(const float2*)(Rrow1 + col);
            float s00 = sfr[j][0] + rv0.x, s01 = sfr[j][1] + rv0.y;
            float s10 = sfr[j][2] + rv1.x, s11 = sfr[j][3] + rv1.y;
            *(float2*)(Srow0 + col) = make_float2(s00, s01);
            *(float2*)(Srow1 + col) = make_float2(s10, s11);
            float mk0 = masksm[j*8 + cbase], mk1 = masksm[j*8 + cbase + 1];
            s00 += mk0; s01 += mk1; s10 += mk0; s11 += mk1;
            sfr[j][0] = s00; sfr[j][1] = s01; sfr[j][2] = s10; sfr[j][3] = s11;
            tmax0 = fmaxf(tmax0, fmaxf(s00, s01));
            tmax1 = fmaxf(tmax1, fmaxf(s10, s11));
        }
        tmax0 = fmaxf(tmax0, __shfl_xor_sync(0xffffffffu, tmax0, 1));
        tmax0 = fmaxf(tmax0, __shfl_xor_sync(0xffffffffu, tmax0, 2));
        tmax1 = fmaxf(tmax1, __shfl_xor_sync(0xffffffffu, tmax1, 1));
        tmax1 = fmaxf(tmax1, __shfl_xor_sync(0xffffffffu, tmax1, 2));

        // ---- online rescale ----
        float mnew0 = fmaxf(mrun0, tmax0);
        float mnew1 = fmaxf(mrun1, tmax1);
        float sc0 = __expf(mrun0 - mnew0);
        float sc1 = __expf(mrun1 - mnew1);
        mrun0 = mnew0; mrun1 = mnew1;
        lrun0 *= sc0; lrun1 *= sc1;
#pragma unroll
        for (int j = 0; j < 8; j++) {
            O[j][0] *= sc0; O[j][1] *= sc0;
            O[j][2] *= sc1; O[j][3] *= sc1;
        }

        // ---- exp + pack P into A-frags (hi/lo) ----
        uint32_t pah[8][4], pal[8][4];
#pragma unroll
        for (int j = 0; j < 16; j++) {
            float e0 = __expf(sfr[j][0] - mnew0);
            float e1 = __expf(sfr[j][1] - mnew0);
            float e2 = __expf(sfr[j][2] - mnew1);
            float e3 = __expf(sfr[j][3] - mnew1);
            lrun0 += e0 + e1;
            lrun1 += e2 + e3;
            __nv_bfloat16 h0 = __float2bfloat16(e0), h1 = __float2bfloat16(e1);
            __nv_bfloat16 h2 = __float2bfloat16(e2), h3 = __float2bfloat16(e3);
            int t = j >> 1, odd = j & 1;
            pah[t][odd*2+0] = pack_bf2(h0, h1);
            pah[t][odd*2+1] = pack_bf2(h2, h3);
            pal[t][odd*2+0] = pack_bf2(__float2bfloat16(e0 - __bfloat162float(h0)),
                                       __float2bfloat16(e1 - __bfloat162float(h1)));
            pal[t][odd*2+1] = pack_bf2(__float2bfloat16(e2 - __bfloat162float(h2)),
                                       __float2bfloat16(e3 - __bfloat162float(h3)));
        }

        // ---- O += P V (3-split) ----
#pragma unroll
        for (int t = 0; t < 8; t++) {
            int sub = t >> 2, ks = t & 3;
            const uint32_t colb = (uint32_t)(ks*32 + lkh);
#pragma unroll
            for (int nj = 0; nj < 4; nj++) {
                uint32_t sw = swz((uint32_t)(nj*16 + lrow) * 128 + colb);
                uint32_t vv[4];
                ldmx4(vv, sb + FA_OF_V + sub*8192 + sw);
                mma16816(O[2*nj+0], pah[t], vv[0], vv[2]);
                mma16816(O[2*nj+1], pah[t], vv[1], vv[3]);
                mma16816(O[2*nj+0], pal[t], vv[0], vv[2]);
                mma16816(O[2*nj+1], pal[t], vv[1], vv[3]);
                ldmx4(vv, sb + FA_OF_V + 16384 + sub*8192 + sw);
                mma16816(O[2*nj+0], pah[t], vv[0], vv[2]);
                mma16816(O[2*nj+1], pah[t], vv[1], vv[3]);
            }
        }
        __syncthreads();
    }

    // ---- finalize ----
    lrun0 += __shfl_xor_sync(0xffffffffu, lrun0, 1);
    lrun0 += __shfl_xor_sync(0xffffffffu, lrun0, 2);
    lrun1 += __shfl_xor_sync(0xffffffffu, lrun1, 1);
    lrun1 += __shfl_xor_sync(0xffffffffu, lrun1, 2);
    float rl0 = 1.0f / lrun0;
    float rl1 = 1.0f / lrun1;

    float* c0 = ctx + ((size_t)b*SS + m0 + r0)*DD + h*DH + cbase;
    float* c1 = ctx + ((size_t)b*SS + m0 + r1)*DD + h*DH + cbase;
#pragma unroll
    for (int nj = 0; nj < 8; nj++) {
        *(float2*)(c0 + nj*8) = make_float2(O[nj][0]*rl0, O[nj][1]*rl0);
        *(float2*)(c1 + nj*8) = make_float2(O[nj][2]*rl1, O[nj][3]*rl1);
    }
}

// ---------------------------------------------------------------------------
extern "C" void kernel_launch(void* const* d_in, const int* in_sizes, int n_in,
                              void* d_out, int out_size)
{
    const float* hid  = (const float*)d_in[0];
    const float* mask = (const float*)d_in[1];
    const float* res  = (const float*)d_in[2];
    const float* Wq = (const float*)d_in[3];
    const float* bq = (const float*)d_in[4];
    const float* Wk = (const float*)d_in[5];
    const float* bk = (const float*)d_in[6];
    const float* Wv = (const float*)d_in[7];
    const float* bv = (const float*)d_in[8];

    float* out_ctx    = (float*)d_out;
    float* out_scores = (float*)d_out + (size_t)BB*SS*DD;

    cudaFuncSetAttribute(qkv_mma_kernel,
                         cudaFuncAttributeMaxDynamicSharedMemorySize, QKV_SMEM);
    cudaFuncSetAttribute(fused_attn_kernel,
                         cudaFuncAttributeMaxDynamicSharedMemorySize, FA_SMEM);

    split_kernel<<<(BB*SS*DD + 255)/256, 256>>>(hid, Wq, Wk, Wv);
    qkv_mma_kernel<<<dim3(DD/128, (BB*SS)/128, 3), 256, QKV_SMEM>>>(bq, bk, bv);
    fused_attn_kernel<<<dim3(SS/64, BH), 128, FA_SMEM>>>(res, mask, out_scores, out_ctx);
}

// round 15
// speedup vs baseline: 2.2952x; 1.1097x over previous
#include <cuda_runtime.h>
#include <cuda_bf16.h>
#include <math_constants.h>
#include <cstdint>

// Problem dims (fixed)
#define BB 2
#define SS 2048
#define DD 768
#define HH 12
#define DH 64
#define BH (BB*HH)          // 24
#define ROWS_TOTAL (BB*HH*SS) // 49152

typedef unsigned long long u64;

// Scratch (device globals: sanctioned scratch mechanism)
__device__ __nv_bfloat16 g_hh[BB*SS*DD];     // hidden split-hi
__device__ __nv_bfloat16 g_hl[BB*SS*DD];     // hidden split-lo
__device__ __nv_bfloat16 g_wh[3*DD*DD];      // Wq|Wk|Wv split-hi
__device__ __nv_bfloat16 g_wl[3*DD*DD];      // Wq|Wk|Wv split-lo
__device__ __nv_bfloat16 g_qh[BB*HH*SS*DH];  // Q*0.125 split-hi
__device__ __nv_bfloat16 g_ql[BB*HH*SS*DH];  // Q*0.125 split-lo
__device__ __nv_bfloat16 g_kh[BB*HH*SS*DH];
__device__ __nv_bfloat16 g_kl[BB*HH*SS*DH];
__device__ __nv_bfloat16 g_vth[BB*HH*DH*SS]; // V^T [bh][d][s] split-hi
__device__ __nv_bfloat16 g_vtl[BB*HH*DH*SS]; // V^T split-lo

__device__ __forceinline__ uint32_t smem_u32(const void* p) {
    uint32_t a;
    asm("{ .reg .u64 t; cvta.to.shared.u64 t, %1; cvt.u32.u64 %0, t; }" : "=r"(a) : "l"(p));
    return a;
}
__device__ __forceinline__ void ldmx4(uint32_t* r, uint32_t addr) {
    asm volatile("ldmatrix.sync.aligned.m8n8.x4.shared.b16 {%0,%1,%2,%3}, [%4];"
        : "=r"(r[0]), "=r"(r[1]), "=r"(r[2]), "=r"(r[3]) : "r"(addr));
}
__device__ __forceinline__ void mma16816(float* c, const uint32_t* a, uint32_t b0, uint32_t b1) {
    asm volatile(
        "mma.sync.aligned.m16n8k16.row.col.f32.bf16.bf16.f32 "
        "{%0,%1,%2,%3},{%4,%5,%6,%7},{%8,%9},{%0,%1,%2,%3};"
        : "+f"(c[0]), "+f"(c[1]), "+f"(c[2]), "+f"(c[3])
        : "r"(a[0]), "r"(a[1]), "r"(a[2]), "r"(a[3]), "r"(b0), "r"(b1));
}
__device__ __forceinline__ uint32_t pack_bf2(__nv_bfloat16 a, __nv_bfloat16 b) {
    return (uint32_t)__bfloat16_as_ushort(a) | ((uint32_t)__bfloat16_as_ushort(b) << 16);
}
__device__ __forceinline__ uint32_t swz(uint32_t off) {
    return off ^ ((off >> 3) & 0x70);
}
__device__ __forceinline__ void cp16(uint32_t smem_addr, const void* gptr) {
    asm volatile("cp.async.cg.shared.global [%0], [%1], 16;"
                 :: "r"(smem_addr), "l"(gptr) : "memory");
}
#define CP_COMMIT() asm volatile("cp.async.commit_group;" ::: "memory")

// ---------------------------------------------------------------------------
// K0: split hid and W into bf16 hi/lo pairs.
// ---------------------------------------------------------------------------
__global__ __launch_bounds__(256) void split_kernel(
    const float* __restrict__ hid,
    const float* __restrict__ Wq, const float* __restrict__ Wk,
    const float* __restrict__ Wv)
{
    int i = blockIdx.x * 256 + threadIdx.x;
    if (i < BB*SS*DD) {
        float x = hid[i];
        __nv_bfloat16 h = __float2bfloat16(x);
        g_hh[i] = h;
        g_hl[i] = __float2bfloat16(x - __bfloat162float(h));
    }
    if (i < DD*DD) {
        float x = Wq[i];
        __nv_bfloat16 h = __float2bfloat16(x);
        g_wh[i] = h;
        g_wl[i] = __float2bfloat16(x - __bfloat162float(h));

        x = Wk[i];
        h = __float2bfloat16(x);
        g_wh[DD*DD + i] = h;
        g_wl[DD*DD + i] = __float2bfloat16(x - __bfloat162float(h));

        x = Wv[i];
        h = __float2bfloat16(x);
        g_wh[2*DD*DD + i] = h;
        g_wl[2*DD*DD + i] = __float2bfloat16(x - __bfloat162float(h));
    }
}

// ---------------------------------------------------------------------------
// K1 (mma.sync HMMA 3-split, cp.async double-buffered): QKV projection.
// NT GEMM M=4096, N=768, K=768, tiles 128x128, k-chunks of 64, 2-stage pipe.
// smem: buf[2] x (AH|AL|BH|BL each 16 KB) = 128 KB.
// ---------------------------------------------------------------------------
#define QKV_BUF  65536
#define QKV_SMEM (2*QKV_BUF)

__global__ __launch_bounds__(256) void qkv_mma_kernel(
    const float* __restrict__ bq, const float* __restrict__ bk,
    const float* __restrict__ bv)
{
    extern __shared__ __align__(1024) char smem[];
    const int tid = threadIdx.x;
    const int z = blockIdx.z;
    const int m0 = blockIdx.y * 128;
    const int n0 = blockIdx.x * 128;
    const uint32_t sb = smem_u32(smem);

    const __nv_bfloat16* Wh = g_wh + (size_t)z * DD * DD;
    const __nv_bfloat16* Wl = g_wl + (size_t)z * DD * DD;
    const float* bias = (z == 0) ? bq : (z == 1) ? bk : bv;

    const int wid = tid >> 5, lane = tid & 31;
    const int wm = wid & 3, wn = wid >> 2;
    const int mw0 = wm * 32;
    const int nw0 = wn * 64;
    const int lrow = lane & 15;
    const int lkh  = (lane >> 4) * 16;

    float acc[2][8][4];
#pragma unroll
    for (int i = 0; i < 2; i++)
#pragma unroll
        for (int j = 0; j < 8; j++)
#pragma unroll
            for (int q = 0; q < 4; q++) acc[i][j][q] = 0.f;

    // issue one chunk's stages: A/B hi+lo, 64 k-cols starting at kc
    auto issue_chunk = [&](int kc, uint32_t buf) {
        for (int i = tid; i < 1024; i += 256) {
            int row = i >> 3, u = i & 7;
            uint32_t sw = swz((uint32_t)(row*128 + u*16));
            size_t ga = (size_t)(m0 + row)*DD + kc + u*8;
            cp16(buf + sw,         g_hh + ga);
            cp16(buf + 16384 + sw, g_hl + ga);
            size_t gb = (size_t)(n0 + row)*DD + kc + u*8;
            cp16(buf + 32768 + sw, Wh + gb);
            cp16(buf + 49152 + sw, Wl + gb);
        }
    };

    issue_chunk(0, sb);
    CP_COMMIT();

    for (int c = 0; c < 12; c++) {
        if (c + 1 < 12) {
            issue_chunk((c + 1) * 64, sb + (uint32_t)((c + 1) & 1) * QKV_BUF);
            CP_COMMIT();
            asm volatile("cp.async.wait_group 1;" ::: "memory");
        } else {
            asm volatile("cp.async.wait_group 0;" ::: "memory");
        }
        __syncthreads();

        const uint32_t buf = sb + (uint32_t)(c & 1) * QKV_BUF;
#pragma unroll
        for (int ks = 0; ks < 4; ks++) {
            const uint32_t colb = (uint32_t)(ks*32 + lkh);
            uint32_t afh[2][4], afl[2][4];
#pragma unroll
            for (int mi = 0; mi < 2; mi++) {
                uint32_t sw = swz((uint32_t)(mw0 + mi*16 + lrow) * 128 + colb);
                ldmx4(afh[mi], buf + sw);
                ldmx4(afl[mi], buf + 16384 + sw);
            }
            uint32_t bfh[4][4], bfl[4][4];
#pragma unroll
            for (int nj = 0; nj < 4; nj++) {
                uint32_t sw = swz((uint32_t)(nw0 + nj*16 + lrow) * 128 + colb);
                ldmx4(bfh[nj], buf + 32768 + sw);
                ldmx4(bfl[nj], buf + 49152 + sw);
            }
#pragma unroll
            for (int mi = 0; mi < 2; mi++)
#pragma unroll
                for (int nj = 0; nj < 4; nj++) {
                    mma16816(acc[mi][nj*2+0], afh[mi], bfh[nj][0], bfh[nj][2]);
                    mma16816(acc[mi][nj*2+1], afh[mi], bfh[nj][1], bfh[nj][3]);
                    mma16816(acc[mi][nj*2+0], afh[mi], bfl[nj][0], bfl[nj][2]);
                    mma16816(acc[mi][nj*2+1], afh[mi], bfl[nj][1], bfl[nj][3]);
                    mma16816(acc[mi][nj*2+0], afl[mi], bfh[nj][0], bfh[nj][2]);
                    mma16816(acc[mi][nj*2+1], afl[mi], bfh[nj][1], bfh[nj][3]);
                }
        }
        __syncthreads();
    }

    const float sc = (z == 0) ? 0.125f : 1.0f;
    __nv_bfloat16* oh = (z == 0) ? g_qh : g_kh;
    __nv_bfloat16* ol = (z == 0) ? g_ql : g_kl;

#pragma unroll
    for (int mi = 0; mi < 2; mi++) {
#pragma unroll
        for (int half = 0; half < 2; half++) {
            int m = m0 + mw0 + mi*16 + (lane >> 2) + half*8;
            int b = m >> 11, s = m & 2047;
#pragma unroll
            for (int nj = 0; nj < 8; nj++) {
                int n = n0 + nw0 + nj*8 + (lane & 3)*2;
                float x0 = acc[mi][nj][half*2+0] + bias[n];
                float x1 = acc[mi][nj][half*2+1] + bias[n+1];
                if (z == 2) {
                    int h = n >> 6, d = n & 63;
                    __nv_bfloat16 h0 = __float2bfloat16(x0);
                    __nv_bfloat16 h1 = __float2bfloat16(x1);
                    size_t i0 = ((size_t)((b*HH + h)*DH + d))*SS + s;
                    size_t i1 = ((size_t)((b*HH + h)*DH + d + 1))*SS + s;
                    g_vth[i0] = h0;
                    g_vtl[i0] = __float2bfloat16(x0 - __bfloat162float(h0));
                    g_vth[i1] = h1;
                    g_vtl[i1] = __float2bfloat16(x1 - __bfloat162float(h1));
                } else {
                    x0 *= sc; x1 *= sc;
                    int h = n >> 6, d = n & 63;
                    __nv_bfloat16 h0 = __float2bfloat16(x0);
                    __nv_bfloat16 h1 = __float2bfloat16(x1);
                    size_t idx = (((size_t)(b*HH + h)*SS + s) << 6) + d;
                    *(uint32_t*)(oh + idx) = pack_bf2(h0, h1);
                    *(uint32_t*)(ol + idx) = pack_bf2(
                        __float2bfloat16(x0 - __bfloat162float(h0)),
                        __float2bfloat16(x1 - __bfloat162float(h1)));
                }
            }
        }
    }
}

// ---------------------------------------------------------------------------
// K2 (fused flash attention, cp.async pipelined):
// K/mask double-buffered; V issued per-iter and awaited with wait_group 1.
// smem: Kbuf0 32K | Kbuf1 32K (Q staged here first) | VH+VL 32K | mask 2x512
// ---------------------------------------------------------------------------
#define FA_OF_V  65536
#define FA_OF_MK 98304
#define FA_SMEM  (98304 + 1024)

__global__ __launch_bounds__(128, 2) void fused_attn_kernel(
    const float* __restrict__ res, const float* __restrict__ mask,
    float* __restrict__ out_scores, float* __restrict__ ctx)
{
    extern __shared__ __align__(1024) char smem[];
    const int tid = threadIdx.x;
    const int bh = blockIdx.y;
    const int b = bh / HH, h = bh % HH;
    const int m0 = blockIdx.x * 64;
    const uint32_t sb = smem_u32(smem);

    const int wid = tid >> 5, lane = tid & 31;
    const int lrow = lane & 15;
    const int lkh  = (lane >> 4) * 16;
    const int cbase = (lane & 3) * 2;
    const int wrow = wid * 16;

    // --- Stage Q hi/lo (64x64) into Kbuf1 region; load resident A-frags ---
    {
        const uint4* sqh = (const uint4*)(g_qh + (size_t)(bh*SS + m0)*DH);
        const uint4* sql = (const uint4*)(g_ql + (size_t)(bh*SS + m0)*DH);
        for (int i = tid; i < 512; i += 128) {
            uint32_t sw = swz((uint32_t)i * 16);
            *(uint4*)(smem + 32768 + sw) = sqh[i];
            *(uint4*)(smem + 32768 + 8192 + sw) = sql[i];
        }
    }
    __syncthreads();

    uint32_t qa_h[4][4], qa_l[4][4];
#pragma unroll
    for (int t = 0; t < 4; t++) {
        uint32_t sw = swz((uint32_t)(wrow + lrow) * 128 + t*32 + lkh);
        ldmx4(qa_h[t], sb + 32768 + sw);
        ldmx4(qa_l[t], sb + 32768 + 8192 + sw);
    }
    __syncthreads();   // Q frags in regs; Kbuf1 free for prefetch reuse

    const __nv_bfloat16* vth = g_vth + (size_t)(bh*DH)*SS;
    const __nv_bfloat16* vtl = g_vtl + (size_t)(bh*DH)*SS;
    const __nv_bfloat16* kph = g_kh + (size_t)(bh*SS)*DH;
    const __nv_bfloat16* kpl = g_kl + (size_t)(bh*SS)*DH;
    const float* mask_g = mask + (size_t)b*SS;

    // --- prefetch chunk 0: K + mask -> buf0 ---
    {
        const uint4* skh = (const uint4*)kph;
        const uint4* skl = (const uint4*)kpl;
        for (int i = tid; i < 1024; i += 128) {
            uint32_t sw = swz((uint32_t)i * 16);
            cp16(sb + sw, skh + i);
            cp16(sb + 16384 + sw, skl + i);
        }
        if (tid < 32) cp16(sb + FA_OF_MK + tid*16, mask_g + tid*4);
    }
    CP_COMMIT();

    // --- running stats + O accumulator ---
    float mrun0 = -CUDART_INF_F, mrun1 = -CUDART_INF_F;
    float lrun0 = 0.f, lrun1 = 0.f;
    float O[8][4];
#pragma unroll
    for (int j = 0; j < 8; j++)
#pragma unroll
        for (int q = 0; q < 4; q++) O[j][q] = 0.f;

    const int r0 = wrow + (lane >> 2);
    const int r1 = r0 + 8;
    const float* Rrow0 = res + (size_t)bh*SS*SS + (size_t)(m0 + r0)*SS;
    const float* Rrow1 = res + (size_t)bh*SS*SS + (size_t)(m0 + r1)*SS;
    float* Srow0 = out_scores + (size_t)bh*SS*SS + (size_t)(m0 + r0)*SS;
    float* Srow1 = out_scores + (size_t)bh*SS*SS + (size_t)(m0 + r1)*SS;

    for (int it = 0; it < 16; it++) {
        const int cur = it & 1;
        const int n0 = it * 128;

        // ---- issue V(it) ----
        for (int i = tid; i < 1024; i += 128) {
            int sub = i >> 9, rem = i & 511;
            int d = rem >> 3, u = rem & 7;
            size_t g = (size_t)d * SS + n0 + sub*64 + u*8;
            uint32_t sw = swz((uint32_t)(d*128 + u*16));
            cp16(sb + FA_OF_V + sub*8192 + sw, vth + g);
            cp16(sb + FA_OF_V + 16384 + sub*8192 + sw, vtl + g);
        }
        CP_COMMIT();

        // ---- issue K(it+1) + mask(it+1) into other buffer ----
        if (it + 1 < 16) {
            const int nn = n0 + 128;
            const uint4* skh = (const uint4*)(kph + (size_t)nn*DH);
            const uint4* skl = (const uint4*)(kpl + (size_t)nn*DH);
            const uint32_t kb = (uint32_t)(1 - cur) * 32768;
            for (int i = tid; i < 1024; i += 128) {
                uint32_t sw = swz((uint32_t)i * 16);
                cp16(sb + kb + sw, skh + i);
                cp16(sb + kb + 16384 + sw, skl + i);
            }
            if (tid < 32) cp16(sb + FA_OF_MK + (1-cur)*512 + tid*16, mask_g + nn + tid*4);
            CP_COMMIT();
            asm volatile("cp.async.wait_group 1;" ::: "memory");
        } else {
            asm volatile("cp.async.wait_group 0;" ::: "memory");
        }
        __syncthreads();

        const uint32_t kb = (uint32_t)cur * 32768;
        const float* masksm = (const float*)(smem + FA_OF_MK + cur*512);

        // ---- S = Qs K^T (3-split) ----
        float sfr[16][4];
#pragma unroll
        for (int j = 0; j < 16; j++)
#pragma unroll
            for (int q = 0; q < 4; q++) sfr[j][q] = 0.f;

#pragma unroll
        for (int kt = 0; kt < 4; kt++) {
            const uint32_t colb = (uint32_t)(kt*32 + lkh);
#pragma unroll
            for (int j = 0; j < 8; j++) {
                uint32_t sw = swz((uint32_t)(j*16 + lrow) * 128 + colb);
                uint32_t bb[4];
                ldmx4(bb, sb + kb + sw);
                mma16816(sfr[2*j+0], qa_h[kt], bb[0], bb[2]);
                mma16816(sfr[2*j+1], qa_h[kt], bb[1], bb[3]);
                mma16816(sfr[2*j+0], qa_l[kt], bb[0], bb[2]);
                mma16816(sfr[2*j+1], qa_l[kt], bb[1], bb[3]);
                ldmx4(bb, sb + kb + 16384 + sw);
                mma16816(sfr[2*j+0], qa_h[kt], bb[0], bb[2]);
                mma16816(sfr[2*j+1], qa_h[kt], bb[1], bb[3]);
            }
        }

        // ---- +res, write scores, +mask, tile max ----
        float tmax0 = -CUDART_INF_F, tmax1 = -CUDART_INF_F;
#pragma unroll
        for (int j = 0; j < 16; j++) {
            int col = n0 + j*8 + cbase;
            float2 rv0 = *(const float2*)(Rrow0 + col);
            float2 rv1 = *(const float2*)(Rrow1 + col);
            float s00 = sfr[j][0] + rv0.x, s01 = sfr[j][1] + rv0.y;
            float s10 = sfr[j][2] + rv1.x, s11 = sfr[j][3] + rv1.y;
            *(float2*)(Srow0 + col) = make_float2(s00, s01);
            *(float2*)(Srow1 + col) = make_float2(s10, s11);
            float mk0 = masksm[j*8 + cbase], mk1 = masksm[j*8 + cbase + 1];
            s00 += mk0; s01 += mk1; s10 += mk0; s11 += mk1;
            sfr[j][0] = s00; sfr[j][1] = s01; sfr[j][2] = s10; sfr[j][3] = s11;
            tmax0 = fmaxf(tmax0, fmaxf(s00, s01));
            tmax1 = fmaxf(tmax1, fmaxf(s10, s11));
        }
        tmax0 = fmaxf(tmax0, __shfl_xor_sync(0xffffffffu, tmax0, 1));
        tmax0 = fmaxf(tmax0, __shfl_xor_sync(0xffffffffu, tmax0, 2));
        tmax1 = fmaxf(tmax1, __shfl_xor_sync(0xffffffffu, tmax1, 1));
        tmax1 = fmaxf(tmax1, __shfl_xor_sync(0xffffffffu, tmax1, 2));

        // ---- online rescale ----
        float mnew0 = fmaxf(mrun0, tmax0);
        float mnew1 = fmaxf(mrun1, tmax1);
        float sc0 = __expf(mrun0 - mnew0);
        float sc1 = __expf(mrun1 - mnew1);
        mrun0 = mnew0; mrun1 = mnew1;
        lrun0 *= sc0; lrun1 *= sc1;
#pragma unroll
        for (int j = 0; j < 8; j++) {
            O[j][0] *= sc0; O[j][1] *= sc0;
            O[j][2] *= sc1; O[j][3] *= sc1;
        }

        // ---- exp + pack P into A-frags (hi/lo) ----
        uint32_t pah[8][4], pal[8][4];
#pragma unroll
        for (int j = 0; j < 16; j++) {
            float e0 = __expf(sfr[j][0] - mnew0);
            float e1 = __expf(sfr[j][1] - mnew0);
            float e2 = __expf(sfr[j][2] - mnew1);
            float e3 = __expf(sfr[j][3] - mnew1);
            lrun0 += e0 + e1;
            lrun1 += e2 + e3;
            __nv_bfloat16 h0 = __float2bfloat16(e0), h1 = __float2bfloat16(e1);
            __nv_bfloat16 h2 = __float2bfloat16(e2), h3 = __float2bfloat16(e3);
            int t = j >> 1, odd = j & 1;
            pah[t][odd*2+0] = pack_bf2(h0, h1);
            pah[t][odd*2+1] = pack_bf2(h2, h3);
            pal[t][odd*2+0] = pack_bf2(__float2bfloat16(e0 - __bfloat162float(h0)),
                                       __float2bfloat16(e1 - __bfloat162float(h1)));
            pal[t][odd*2+1] = pack_bf2(__float2bfloat16(e2 - __bfloat162float(h2)),
                                       __float2bfloat16(e3 - __bfloat162float(h3)));
        }

        // ---- O += P V (3-split) ----
#pragma unroll
        for (int t = 0; t < 8; t++) {
            int sub = t >> 2, ks = t & 3;
            const uint32_t colb = (uint32_t)(ks*32 + lkh);
#pragma unroll
            for (int nj = 0; nj < 4; nj++) {
                uint32_t sw = swz((uint32_t)(nj*16 + lrow) * 128 + colb);
                uint32_t vv[4];
                ldmx4(vv, sb + FA_OF_V + sub*8192 + sw);
                mma16816(O[2*nj+0], pah[t], vv[0], vv[2]);
                mma16816(O[2*nj+1], pah[t], vv[1], vv[3]);
                mma16816(O[2*nj+0], pal[t], vv[0], vv[2]);
                mma16816(O[2*nj+1], pal[t], vv[1], vv[3]);
                ldmx4(vv, sb + FA_OF_V + 16384 + sub*8192 + sw);
                mma16816(O[2*nj+0], pah[t], vv[0], vv[2]);
                mma16816(O[2*nj+1], pah[t], vv[1], vv[3]);
            }
        }
        __syncthreads();
    }

    // ---- finalize ----
    lrun0 += __shfl_xor_sync(0xffffffffu, lrun0, 1);
    lrun0 += __shfl_xor_sync(0xffffffffu, lrun0, 2);
    lrun1 += __shfl_xor_sync(0xffffffffu, lrun1, 1);
    lrun1 += __shfl_xor_sync(0xffffffffu, lrun1, 2);
    float rl0 = 1.0f / lrun0;
    float rl1 = 1.0f / lrun1;

    float* c0 = ctx + ((size_t)b*SS + m0 + r0)*DD + h*DH + cbase;
    float* c1 = ctx + ((size_t)b*SS + m0 + r1)*DD + h*DH + cbase;
#pragma unroll
    for (int nj = 0; nj < 8; nj++) {
        *(float2*)(c0 + nj*8) = make_float2(O[nj][0]*rl0, O[nj][1]*rl0);
        *(float2*)(c1 + nj*8) = make_float2(O[nj][2]*rl1, O[nj][3]*rl1);
    }
}

// ---------------------------------------------------------------------------
extern "C" void kernel_launch(void* const* d_in, const int* in_sizes, int n_in,
                              void* d_out, int out_size)
{
    const float* hid  = (const float*)d_in[0];
    const float* mask = (const float*)d_in[1];
    const float* res  = (const float*)d_in[2];
    const float* Wq = (const float*)d_in[3];
    const float* bq = (const float*)d_in[4];
    const float* Wk = (const float*)d_in[5];
    const float* bk = (const float*)d_in[6];
    const float* Wv = (const float*)d_in[7];
    const float* bv = (const float*)d_in[8];

    float* out_ctx    = (float*)d_out;
    float* out_scores = (float*)d_out + (size_t)BB*SS*DD;

    cudaFuncSetAttribute(qkv_mma_kernel,
                         cudaFuncAttributeMaxDynamicSharedMemorySize, QKV_SMEM);
    cudaFuncSetAttribute(fused_attn_kernel,
                         cudaFuncAttributeMaxDynamicSharedMemorySize, FA_SMEM);

    split_kernel<<<(BB*SS*DD + 255)/256, 256>>>(hid, Wq, Wk, Wv);
    qkv_mma_kernel<<<dim3(DD/128, (BB*SS)/128, 3), 256, QKV_SMEM>>>(bq, bk, bv);
    fused_attn_kernel<<<dim3(SS/64, BH), 128, FA_SMEM>>>(res, mask, out_scores, out_ctx);
}

// round 16
// speedup vs baseline: 2.3927x; 1.0425x over previous
#include <cuda_runtime.h>
#include <cuda_bf16.h>
#include <math_constants.h>
#include <cstdint>

// Problem dims (fixed)
#define BB 2
#define SS 2048
#define DD 768
#define HH 12
#define DH 64
#define BH (BB*HH)          // 24
#define ROWS_TOTAL (BB*HH*SS) // 49152

typedef unsigned long long u64;

// Scratch (device globals: sanctioned scratch mechanism)
__device__ __nv_bfloat16 g_hh[BB*SS*DD];     // hidden split-hi
__device__ __nv_bfloat16 g_hl[BB*SS*DD];     // hidden split-lo
__device__ __nv_bfloat16 g_wh[3*DD*DD];      // Wq|Wk|Wv split-hi
__device__ __nv_bfloat16 g_wl[3*DD*DD];      // Wq|Wk|Wv split-lo
__device__ __nv_bfloat16 g_qh[BB*HH*SS*DH];  // Q*0.125 split-hi
__device__ __nv_bfloat16 g_ql[BB*HH*SS*DH];  // Q*0.125 split-lo
__device__ __nv_bfloat16 g_kh[BB*HH*SS*DH];
__device__ __nv_bfloat16 g_kl[BB*HH*SS*DH];
__device__ __nv_bfloat16 g_vth[BB*HH*DH*SS]; // V^T [bh][d][s] split-hi
__device__ __nv_bfloat16 g_vtl[BB*HH*DH*SS]; // V^T split-lo

__device__ __forceinline__ uint32_t smem_u32(const void* p) {
    uint32_t a;
    asm("{ .reg .u64 t; cvta.to.shared.u64 t, %1; cvt.u32.u64 %0, t; }" : "=r"(a) : "l"(p));
    return a;
}
__device__ __forceinline__ void ldmx4(uint32_t* r, uint32_t addr) {
    asm volatile("ldmatrix.sync.aligned.m8n8.x4.shared.b16 {%0,%1,%2,%3}, [%4];"
        : "=r"(r[0]), "=r"(r[1]), "=r"(r[2]), "=r"(r[3]) : "r"(addr));
}
__device__ __forceinline__ void mma16816(float* c, const uint32_t* a, uint32_t b0, uint32_t b1) {
    asm volatile(
        "mma.sync.aligned.m16n8k16.row.col.f32.bf16.bf16.f32 "
        "{%0,%1,%2,%3},{%4,%5,%6,%7},{%8,%9},{%0,%1,%2,%3};"
        : "+f"(c[0]), "+f"(c[1]), "+f"(c[2]), "+f"(c[3])
        : "r"(a[0]), "r"(a[1]), "r"(a[2]), "r"(a[3]), "r"(b0), "r"(b1));
}
__device__ __forceinline__ uint32_t pack_bf2(__nv_bfloat16 a, __nv_bfloat16 b) {
    return (uint32_t)__bfloat16_as_ushort(a) | ((uint32_t)__bfloat16_as_ushort(b) << 16);
}
__device__ __forceinline__ uint32_t swz(uint32_t off) {
    return off ^ ((off >> 3) & 0x70);
}
__device__ __forceinline__ void cp16(uint32_t smem_addr, const void* gptr) {
    asm volatile("cp.async.cg.shared.global [%0], [%1], 16;"
                 :: "r"(smem_addr), "l"(gptr) : "memory");
}
#define CP_COMMIT() asm volatile("cp.async.commit_group;" ::: "memory")

// ---------------------------------------------------------------------------
// K0: split hid and W into bf16 hi/lo pairs.
// ---------------------------------------------------------------------------
__global__ __launch_bounds__(256) void split_kernel(
    const float* __restrict__ hid,
    const float* __restrict__ Wq, const float* __restrict__ Wk,
    const float* __restrict__ Wv)
{
    int i = blockIdx.x * 256 + threadIdx.x;
    if (i < BB*SS*DD) {
        float x = hid[i];
        __nv_bfloat16 h = __float2bfloat16(x);
        g_hh[i] = h;
        g_hl[i] = __float2bfloat16(x - __bfloat162float(h));
    }
    if (i < DD*DD) {
        float x = Wq[i];
        __nv_bfloat16 h = __float2bfloat16(x);
        g_wh[i] = h;
        g_wl[i] = __float2bfloat16(x - __bfloat162float(h));

        x = Wk[i];
        h = __float2bfloat16(x);
        g_wh[DD*DD + i] = h;
        g_wl[DD*DD + i] = __float2bfloat16(x - __bfloat162float(h));

        x = Wv[i];
        h = __float2bfloat16(x);
        g_wh[2*DD*DD + i] = h;
        g_wl[2*DD*DD + i] = __float2bfloat16(x - __bfloat162float(h));
    }
}

// ---------------------------------------------------------------------------
// K1 (mma.sync HMMA 3-split, cp.async double-buffered): QKV projection.
// ---------------------------------------------------------------------------
#define QKV_BUF  65536
#define QKV_SMEM (2*QKV_BUF)

__global__ __launch_bounds__(256) void qkv_mma_kernel(
    const float* __restrict__ bq, const float* __restrict__ bk,
    const float* __restrict__ bv)
{
    extern __shared__ __align__(1024) char smem[];
    const int tid = threadIdx.x;
    const int z = blockIdx.z;
    const int m0 = blockIdx.y * 128;
    const int n0 = blockIdx.x * 128;
    const uint32_t sb = smem_u32(smem);

    const __nv_bfloat16* Wh = g_wh + (size_t)z * DD * DD;
    const __nv_bfloat16* Wl = g_wl + (size_t)z * DD * DD;
    const float* bias = (z == 0) ? bq : (z == 1) ? bk : bv;

    const int wid = tid >> 5, lane = tid & 31;
    const int wm = wid & 3, wn = wid >> 2;
    const int mw0 = wm * 32;
    const int nw0 = wn * 64;
    const int lrow = lane & 15;
    const int lkh  = (lane >> 4) * 16;

    float acc[2][8][4];
#pragma unroll
    for (int i = 0; i < 2; i++)
#pragma unroll
        for (int j = 0; j < 8; j++)
#pragma unroll
            for (int q = 0; q < 4; q++) acc[i][j][q] = 0.f;

    auto issue_chunk = [&](int kc, uint32_t buf) {
        for (int i = tid; i < 1024; i += 256) {
            int row = i >> 3, u = i & 7;
            uint32_t sw = swz((uint32_t)(row*128 + u*16));
            size_t ga = (size_t)(m0 + row)*DD + kc + u*8;
            cp16(buf + sw,         g_hh + ga);
            cp16(buf + 16384 + sw, g_hl + ga);
            size_t gb = (size_t)(n0 + row)*DD + kc + u*8;
            cp16(buf + 32768 + sw, Wh + gb);
            cp16(buf + 49152 + sw, Wl + gb);
        }
    };

    issue_chunk(0, sb);
    CP_COMMIT();

    for (int c = 0; c < 12; c++) {
        if (c + 1 < 12) {
            issue_chunk((c + 1) * 64, sb + (uint32_t)((c + 1) & 1) * QKV_BUF);
            CP_COMMIT();
            asm volatile("cp.async.wait_group 1;" ::: "memory");
        } else {
            asm volatile("cp.async.wait_group 0;" ::: "memory");
        }
        __syncthreads();

        const uint32_t buf = sb + (uint32_t)(c & 1) * QKV_BUF;
#pragma unroll
        for (int ks = 0; ks < 4; ks++) {
            const uint32_t colb = (uint32_t)(ks*32 + lkh);
            uint32_t afh[2][4], afl[2][4];
#pragma unroll
            for (int mi = 0; mi < 2; mi++) {
                uint32_t sw = swz((uint32_t)(mw0 + mi*16 + lrow) * 128 + colb);
                ldmx4(afh[mi], buf + sw);
                ldmx4(afl[mi], buf + 16384 + sw);
            }
            uint32_t bfh[4][4], bfl[4][4];
#pragma unroll
            for (int nj = 0; nj < 4; nj++) {
                uint32_t sw = swz((uint32_t)(nw0 + nj*16 + lrow) * 128 + colb);
                ldmx4(bfh[nj], buf + 32768 + sw);
                ldmx4(bfl[nj], buf + 49152 + sw);
            }
#pragma unroll
            for (int mi = 0; mi < 2; mi++)
#pragma unroll
                for (int nj = 0; nj < 4; nj++) {
                    mma16816(acc[mi][nj*2+0], afh[mi], bfh[nj][0], bfh[nj][2]);
                    mma16816(acc[mi][nj*2+1], afh[mi], bfh[nj][1], bfh[nj][3]);
                    mma16816(acc[mi][nj*2+0], afh[mi], bfl[nj][0], bfl[nj][2]);
                    mma16816(acc[mi][nj*2+1], afh[mi], bfl[nj][1], bfl[nj][3]);
                    mma16816(acc[mi][nj*2+0], afl[mi], bfh[nj][0], bfh[nj][2]);
                    mma16816(acc[mi][nj*2+1], afl[mi], bfh[nj][1], bfh[nj][3]);
                }
        }
        __syncthreads();
    }

    const float sc = (z == 0) ? 0.125f : 1.0f;
    __nv_bfloat16* oh = (z == 0) ? g_qh : g_kh;
    __nv_bfloat16* ol = (z == 0) ? g_ql : g_kl;

#pragma unroll
    for (int mi = 0; mi < 2; mi++) {
#pragma unroll
        for (int half = 0; half < 2; half++) {
            int m = m0 + mw0 + mi*16 + (lane >> 2) + half*8;
            int b = m >> 11, s = m & 2047;
#pragma unroll
            for (int nj = 0; nj < 8; nj++) {
                int n = n0 + nw0 + nj*8 + (lane & 3)*2;
                float x0 = acc[mi][nj][half*2+0] + bias[n];
                float x1 = acc[mi][nj][half*2+1] + bias[n+1];
                if (z == 2) {
                    int h = n >> 6, d = n & 63;
                    __nv_bfloat16 h0 = __float2bfloat16(x0);
                    __nv_bfloat16 h1 = __float2bfloat16(x1);
                    size_t i0 = ((size_t)((b*HH + h)*DH + d))*SS + s;
                    size_t i1 = ((size_t)((b*HH + h)*DH + d + 1))*SS + s;
                    g_vth[i0] = h0;
                    g_vtl[i0] = __float2bfloat16(x0 - __bfloat162float(h0));
                    g_vth[i1] = h1;
                    g_vtl[i1] = __float2bfloat16(x1 - __bfloat162float(h1));
                } else {
                    x0 *= sc; x1 *= sc;
                    int h = n >> 6, d = n & 63;
                    __nv_bfloat16 h0 = __float2bfloat16(x0);
                    __nv_bfloat16 h1 = __float2bfloat16(x1);
                    size_t idx = (((size_t)(b*HH + h)*SS + s) << 6) + d;
                    *(uint32_t*)(oh + idx) = pack_bf2(h0, h1);
                    *(uint32_t*)(ol + idx) = pack_bf2(
                        __float2bfloat16(x0 - __bfloat162float(h0)),
                        __float2bfloat16(x1 - __bfloat162float(h1)));
                }
            }
        }
    }
}

// ---------------------------------------------------------------------------
// K2 (fused flash attention, cp.async pipelined, 64-col chunks, 3 CTAs/SM):
// smem: Kbuf0 16K | Kbuf1 16K (Q staged here first) | VH 8K | VL 8K | mask 2x256
// ---------------------------------------------------------------------------
#define FA_OF_V  32768
#define FA_OF_MK 49152
#define FA_SMEM  (49152 + 512)

__global__ __launch_bounds__(128, 3) void fused_attn_kernel(
    const float* __restrict__ res, const float* __restrict__ mask,
    float* __restrict__ out_scores, float* __restrict__ ctx)
{
    extern __shared__ __align__(1024) char smem[];
    const int tid = threadIdx.x;
    const int bh = blockIdx.y;
    const int b = bh / HH, h = bh % HH;
    const int m0 = blockIdx.x * 64;
    const uint32_t sb = smem_u32(smem);

    const int wid = tid >> 5, lane = tid & 31;
    const int lrow = lane & 15;
    const int lkh  = (lane >> 4) * 16;
    const int cbase = (lane & 3) * 2;
    const int wrow = wid * 16;

    // --- Stage Q hi/lo (64x64) into Kbuf1; load resident A-frags ---
    {
        const uint4* sqh = (const uint4*)(g_qh + (size_t)(bh*SS + m0)*DH);
        const uint4* sql = (const uint4*)(g_ql + (size_t)(bh*SS + m0)*DH);
        for (int i = tid; i < 512; i += 128) {
            uint32_t sw = swz((uint32_t)i * 16);
            *(uint4*)(smem + 16384 + sw) = sqh[i];
            *(uint4*)(smem + 16384 + 8192 + sw) = sql[i];
        }
    }
    __syncthreads();

    uint32_t qa_h[4][4], qa_l[4][4];
#pragma unroll
    for (int t = 0; t < 4; t++) {
        uint32_t sw = swz((uint32_t)(wrow + lrow) * 128 + t*32 + lkh);
        ldmx4(qa_h[t], sb + 16384 + sw);
        ldmx4(qa_l[t], sb + 16384 + 8192 + sw);
    }
    __syncthreads();   // Q consumed; Kbuf1 free

    const __nv_bfloat16* vth = g_vth + (size_t)(bh*DH)*SS;
    const __nv_bfloat16* vtl = g_vtl + (size_t)(bh*DH)*SS;
    const __nv_bfloat16* kph = g_kh + (size_t)(bh*SS)*DH;
    const __nv_bfloat16* kpl = g_kl + (size_t)(bh*SS)*DH;
    const float* mask_g = mask + (size_t)b*SS;

    // --- prefetch chunk 0: K (64x64 hi/lo) + mask -> buf0 ---
    {
        const uint4* skh = (const uint4*)kph;
        const uint4* skl = (const uint4*)kpl;
        for (int i = tid; i < 512; i += 128) {
            uint32_t sw = swz((uint32_t)i * 16);
            cp16(sb + sw, skh + i);
            cp16(sb + 8192 + sw, skl + i);
        }
        if (tid < 16) cp16(sb + FA_OF_MK + tid*16, mask_g + tid*4);
    }
    CP_COMMIT();

    // --- running stats + O accumulator ---
    float mrun0 = -CUDART_INF_F, mrun1 = -CUDART_INF_F;
    float lrun0 = 0.f, lrun1 = 0.f;
    float O[8][4];
#pragma unroll
    for (int j = 0; j < 8; j++)
#pragma unroll
        for (int q = 0; q < 4; q++) O[j][q] = 0.f;

    const int r0 = wrow + (lane >> 2);
    const int r1 = r0 + 8;
    const float* Rrow0 = res + (size_t)bh*SS*SS + (size_t)(m0 + r0)*SS;
    const float* Rrow1 = res + (size_t)bh*SS*SS + (size_t)(m0 + r1)*SS;
    float* Srow0 = out_scores + (size_t)bh*SS*SS + (size_t)(m0 + r0)*SS;
    float* Srow1 = out_scores + (size_t)bh*SS*SS + (size_t)(m0 + r1)*SS;

    for (int it = 0; it < 32; it++) {
        const int cur = it & 1;
        const int n0 = it * 64;

        // ---- issue V(it): [d 0..63][s 64] hi/lo ----
        for (int i = tid; i < 512; i += 128) {
            int d = i >> 3, u = i & 7;
            size_t g = (size_t)d * SS + n0 + u*8;
            uint32_t sw = swz((uint32_t)(d*128 + u*16));
            cp16(sb + FA_OF_V + sw, vth + g);
            cp16(sb + FA_OF_V + 8192 + sw, vtl + g);
        }
        CP_COMMIT();

        // ---- issue K(it+1) + mask(it+1) ----
        if (it + 1 < 32) {
            const int nn = n0 + 64;
            const uint4* skh = (const uint4*)(kph + (size_t)nn*DH);
            const uint4* skl = (const uint4*)(kpl + (size_t)nn*DH);
            const uint32_t kb = (uint32_t)(1 - cur) * 16384;
            for (int i = tid; i < 512; i += 128) {
                uint32_t sw = swz((uint32_t)i * 16);
                cp16(sb + kb + sw, skh + i);
                cp16(sb + kb + 8192 + sw, skl + i);
            }
            if (tid < 16) cp16(sb + FA_OF_MK + (1-cur)*256 + tid*16, mask_g + nn + tid*4);
            CP_COMMIT();
            asm volatile("cp.async.wait_group 1;" ::: "memory");
        } else {
            asm volatile("cp.async.wait_group 0;" ::: "memory");
        }
        __syncthreads();

        const uint32_t kb = (uint32_t)cur * 16384;
        const float* masksm = (const float*)(smem + FA_OF_MK + cur*256);

        // ---- S = Qs K^T (3-split), 64 cols ----
        float sfr[8][4];
#pragma unroll
        for (int j = 0; j < 8; j++)
#pragma unroll
            for (int q = 0; q < 4; q++) sfr[j][q] = 0.f;

#pragma unroll
        for (int kt = 0; kt < 4; kt++) {
            const uint32_t colb = (uint32_t)(kt*32 + lkh);
#pragma unroll
            for (int j = 0; j < 4; j++) {
                uint32_t sw = swz((uint32_t)(j*16 + lrow) * 128 + colb);
                uint32_t bb[4];
                ldmx4(bb, sb + kb + sw);
                mma16816(sfr[2*j+0], qa_h[kt], bb[0], bb[2]);
                mma16816(sfr[2*j+1], qa_h[kt], bb[1], bb[3]);
                mma16816(sfr[2*j+0], qa_l[kt], bb[0], bb[2]);
                mma16816(sfr[2*j+1], qa_l[kt], bb[1], bb[3]);
                ldmx4(bb, sb + kb + 8192 + sw);
                mma16816(sfr[2*j+0], qa_h[kt], bb[0], bb[2]);
                mma16816(sfr[2*j+1], qa_h[kt], bb[1], bb[3]);
            }
        }

        // ---- +res, write scores, +mask, tile max ----
        float tmax0 = -CUDART_INF_F, tmax1 = -CUDART_INF_F;
#pragma unroll
        for (int j = 0; j < 8; j++) {
            int col = n0 + j*8 + cbase;
            float2 rv0 = *(const float2*)(Rrow0 + col);
            float2 rv1 = *(const float2*)(Rrow1 + col);
            float s00 = sfr[j][0] + rv0.x, s01 = sfr[j][1] + rv0.y;
            float s10 = sfr[j][2] + rv1.x, s11 = sfr[j][3] + rv1.y;
            *(float2*)(Srow0 + col) = make_float2(s00, s01);
            *(float2*)(Srow1 + col) = make_float2(s10, s11);
            float mk0 = masksm[j*8 + cbase], mk1 = masksm[j*8 + cbase + 1];
            s00 += mk0; s01 += mk1; s10 += mk0; s11 += mk1;
            sfr[j][0] = s00; sfr[j][1] = s01; sfr[j][2] = s10; sfr[j][3] = s11;
            tmax0 = fmaxf(tmax0, fmaxf(s00, s01));
            tmax1 = fmaxf(tmax1, fmaxf(s10, s11));
        }
        tmax0 = fmaxf(tmax0, __shfl_xor_sync(0xffffffffu, tmax0, 1));
        tmax0 = fmaxf(tmax0, __shfl_xor_sync(0xffffffffu, tmax0, 2));
        tmax1 = fmaxf(tmax1, __shfl_xor_sync(0xffffffffu, tmax1, 1));
        tmax1 = fmaxf(tmax1, __shfl_xor_sync(0xffffffffu, tmax1, 2));

        // ---- online rescale ----
        float mnew0 = fmaxf(mrun0, tmax0);
        float mnew1 = fmaxf(mrun1, tmax1);
        float sc0 = __expf(mrun0 - mnew0);
        float sc1 = __expf(mrun1 - mnew1);
        mrun0 = mnew0; mrun1 = mnew1;
        lrun0 *= sc0; lrun1 *= sc1;
#pragma unroll
        for (int j = 0; j < 8; j++) {
            O[j][0] *= sc0; O[j][1] *= sc0;
            O[j][2] *= sc1; O[j][3] *= sc1;
        }

        // ---- exp + pack P into A-frags (hi/lo) ----
        uint32_t pah[4][4], pal[4][4];
#pragma unroll
        for (int j = 0; j < 8; j++) {
            float e0 = __expf(sfr[j][0] - mnew0);
            float e1 = __expf(sfr[j][1] - mnew0);
            float e2 = __expf(sfr[j][2] - mnew1);
            float e3 = __expf(sfr[j][3] - mnew1);
            lrun0 += e0 + e1;
            lrun1 += e2 + e3;
            __nv_bfloat16 h0 = __float2bfloat16(e0), h1 = __float2bfloat16(e1);
            __nv_bfloat16 h2 = __float2bfloat16(e2), h3 = __float2bfloat16(e3);
            int t = j >> 1, odd = j & 1;
            pah[t][odd*2+0] = pack_bf2(h0, h1);
            pah[t][odd*2+1] = pack_bf2(h2, h3);
            pal[t][odd*2+0] = pack_bf2(__float2bfloat16(e0 - __bfloat162float(h0)),
                                       __float2bfloat16(e1 - __bfloat162float(h1)));
            pal[t][odd*2+1] = pack_bf2(__float2bfloat16(e2 - __bfloat162float(h2)),
                                       __float2bfloat16(e3 - __bfloat162float(h3)));
        }

        // ---- O += P V (3-split) ----
#pragma unroll
        for (int ks = 0; ks < 4; ks++) {
            const uint32_t colb = (uint32_t)(ks*32 + lkh);
#pragma unroll
            for (int nj = 0; nj < 4; nj++) {
                uint32_t sw = swz((uint32_t)(nj*16 + lrow) * 128 + colb);
                uint32_t vv[4];
                ldmx4(vv, sb + FA_OF_V + sw);
                mma16816(O[2*nj+0], pah[ks], vv[0], vv[2]);
                mma16816(O[2*nj+1], pah[ks], vv[1], vv[3]);
                mma16816(O[2*nj+0], pal[ks], vv[0], vv[2]);
                mma16816(O[2*nj+1], pal[ks], vv[1], vv[3]);
                ldmx4(vv, sb + FA_OF_V + 8192 + sw);
                mma16816(O[2*nj+0], pah[ks], vv[0], vv[2]);
                mma16816(O[2*nj+1], pah[ks], vv[1], vv[3]);
            }
        }
        __syncthreads();
    }

    // ---- finalize ----
    lrun0 += __shfl_xor_sync(0xffffffffu, lrun0, 1);
    lrun0 += __shfl_xor_sync(0xffffffffu, lrun0, 2);
    lrun1 += __shfl_xor_sync(0xffffffffu, lrun1, 1);
    lrun1 += __shfl_xor_sync(0xffffffffu, lrun1, 2);
    float rl0 = 1.0f / lrun0;
    float rl1 = 1.0f / lrun1;

    float* c0 = ctx + ((size_t)b*SS + m0 + r0)*DD + h*DH + cbase;
    float* c1 = ctx + ((size_t)b*SS + m0 + r1)*DD + h*DH + cbase;
#pragma unroll
    for (int nj = 0; nj < 8; nj++) {
        *(float2*)(c0 + nj*8) = make_float2(O[nj][0]*rl0, O[nj][1]*rl0);
        *(float2*)(c1 + nj*8) = make_float2(O[nj][2]*rl1, O[nj][3]*rl1);
    }
}

// ---------------------------------------------------------------------------
extern "C" void kernel_launch(void* const* d_in, const int* in_sizes, int n_in,
                              void* d_out, int out_size)
{
    const float* hid  = (const float*)d_in[0];
    const float* mask = (const float*)d_in[1];
    const float* res  = (const float*)d_in[2];
    const float* Wq = (const float*)d_in[3];
    const float* bq = (const float*)d_in[4];
    const float* Wk = (const float*)d_in[5];
    const float* bk = (const float*)d_in[6];
    const float* Wv = (const float*)d_in[7];
    const float* bv = (const float*)d_in[8];

    float* out_ctx    = (float*)d_out;
    float* out_scores = (float*)d_out + (size_t)BB*SS*DD;

    cudaFuncSetAttribute(qkv_mma_kernel,
                         cudaFuncAttributeMaxDynamicSharedMemorySize, QKV_SMEM);
    cudaFuncSetAttribute(fused_attn_kernel,
                         cudaFuncAttributeMaxDynamicSharedMemorySize, FA_SMEM);

    split_kernel<<<(BB*SS*DD + 255)/256, 256>>>(hid, Wq, Wk, Wv);
    qkv_mma_kernel<<<dim3(DD/128, (BB*SS)/128, 3), 256, QKV_SMEM>>>(bq, bk, bv);
    fused_attn_kernel<<<dim3(SS/64, BH), 128, FA_SMEM>>>(res, mask, out_scores, out_ctx);
}